// round 1
// baseline (speedup 1.0000x reference)
#include <cuda_runtime.h>
#include <math.h>

namespace {

constexpr int Bc = 32, Nc = 96, Dc = 32, Fc = 16;
constexpr int THREADS = 1024;   // = Dc*Dc, thread tid -> A[p=tid>>5][q=tid&31]

__device__ __forceinline__ float sigmoidf_(float x) { return 1.0f / (1.0f + expf(-x)); }

__global__ __launch_bounds__(THREADS, 1)
void mp_layer_kernel(const float* __restrict__ nodes,   // [B, N, D]
                     const float* __restrict__ edges,   // [B, N*N, F]
                     const float* __restrict__ mask,    // [B, N*N, 1] (0/1)
                     const float* __restrict__ W_agg,   // [F, D*D]
                     const float* __restrict__ b_agg,   // [D*D]
                     const float* __restrict__ w_ih,    // [3D, D]
                     const float* __restrict__ w_hh,    // [3D, D]
                     const float* __restrict__ b_ih,    // [3D]
                     const float* __restrict__ b_hh,    // [3D]
                     float* __restrict__ out)           // [B, N, D]
{
    __shared__ float edges_sh[Nc * Fc];     // edge rows for this (b,i)
    __shared__ float mnodes_sh[Nc * Dc];    // nodes[b,j,:] * mask[b, i*N+j]
    __shared__ int   active_sh[Nc];         // compacted list of active j
    __shared__ int   count_sh;
    __shared__ float agg_sh[Dc];
    __shared__ float x1_sh[Dc];
    __shared__ float h1_sh[Dc];
    __shared__ float gi_sh[3 * Dc];
    __shared__ float gh_sh[3 * Dc];

    const int tid  = threadIdx.x;
    const int lane = tid & 31;   // q
    const int p    = tid >> 5;   // p
    const int bi   = blockIdx.x;
    const int b    = bi / Nc;
    const int i    = bi - b * Nc;

    const size_t ebase = ((size_t)b * (Nc * Nc) + (size_t)i * Nc) * Fc;
    const size_t mbase = (size_t)b * (Nc * Nc) + (size_t)i * Nc;
    const size_t nbase = (size_t)b * (Nc * Dc);

    // W_agg column for this thread's (p,q): 16 registers, reused for all edges.
    float Wreg[Fc];
#pragma unroll
    for (int f = 0; f < Fc; f++) Wreg[f] = W_agg[f * (Dc * Dc) + tid];
    const float breg = b_agg[tid];

    // Stage edge rows (96 x 16 floats, contiguous) into SMEM via float4.
    {
        const float4* src = reinterpret_cast<const float4*>(edges + ebase);
        float4*       dst = reinterpret_cast<float4*>(edges_sh);
        if (tid < (Nc * Fc) / 4) dst[tid] = src[tid];
    }
    // Mask-premultiplied source nodes: mnodes[j*32+q] = nodes[b,j,q]*mask[b,e(i,j)]
    for (int k = tid; k < Nc * Dc; k += THREADS) {
        const int j = k >> 5;
        mnodes_sh[k] = nodes[nbase + k] * mask[mbase + j];
    }
    // x1 = nodes[b, i, :] (unmasked, GRU input 1)
    if (tid < Dc) x1_sh[tid] = nodes[nbase + (size_t)i * Dc + tid];

    // Warp 0: compact the list of active edges (mask != 0) via ballot prefix.
    if (tid < 32) {
        int cnt = 0;
#pragma unroll
        for (int r = 0; r < Nc / 32; r++) {
            const int j = r * 32 + lane;
            const bool a = (mask[mbase + j] != 0.0f);
            const unsigned bal = __ballot_sync(0xffffffffu, a);
            if (a) {
                const int pos = cnt + __popc(bal & ((1u << lane) - 1u));
                active_sh[pos] = j;
            }
            cnt += __popc(bal);
        }
        if (lane == 0) count_sh = cnt;
    }
    __syncthreads();

    // Main loop: only active edges, no branches inside.
    const int cnt = count_sh;
    float acc = 0.0f;
    for (int a = 0; a < cnt; a++) {
        const int j = active_sh[a];
        const float4* ev = reinterpret_cast<const float4*>(edges_sh + j * Fc);
        const float4 e0 = ev[0], e1 = ev[1], e2 = ev[2], e3 = ev[3];
        float s = breg;
        s = fmaf(e0.x, Wreg[0],  s);  s = fmaf(e0.y, Wreg[1],  s);
        s = fmaf(e0.z, Wreg[2],  s);  s = fmaf(e0.w, Wreg[3],  s);
        s = fmaf(e1.x, Wreg[4],  s);  s = fmaf(e1.y, Wreg[5],  s);
        s = fmaf(e1.z, Wreg[6],  s);  s = fmaf(e1.w, Wreg[7],  s);
        s = fmaf(e2.x, Wreg[8],  s);  s = fmaf(e2.y, Wreg[9],  s);
        s = fmaf(e2.z, Wreg[10], s);  s = fmaf(e2.w, Wreg[11], s);
        s = fmaf(e3.x, Wreg[12], s);  s = fmaf(e3.y, Wreg[13], s);
        s = fmaf(e3.z, Wreg[14], s);  s = fmaf(e3.w, Wreg[15], s);
        s = fmaxf(s, 0.0f);                         // ReLU
        acc = fmaf(s, mnodes_sh[j * Dc + lane], acc);  // * masked node, accumulate over j
    }
    // Reduce over q (lanes) -> message/agg component p.
#pragma unroll
    for (int o = 16; o; o >>= 1) acc += __shfl_xor_sync(0xffffffffu, acc, o);
    if (lane == 0) agg_sh[p] = acc;
    __syncthreads();

    // ---- GRU combiner (row (b,i)), h0 = 0 ----
    // Step 1: x = nodes[b,i,:], h = 0  =>  gh = b_hh
    if (tid < 3 * Dc) {
        const float* wrow = w_ih + tid * Dc;
        float g = b_ih[tid];
#pragma unroll
        for (int d = 0; d < Dc; d++) g = fmaf(x1_sh[d], wrow[d], g);
        gi_sh[tid] = g;
    }
    __syncthreads();
    if (tid < Dc) {
        const float r = sigmoidf_(gi_sh[tid] + b_hh[tid]);
        const float z = sigmoidf_(gi_sh[Dc + tid] + b_hh[Dc + tid]);
        const float n = tanhf(gi_sh[2 * Dc + tid] + r * b_hh[2 * Dc + tid]);
        h1_sh[tid] = (1.0f - z) * n;   // + z*h0, h0 = 0
    }
    __syncthreads();
    // Step 2: x = agg, h = h1
    if (tid < 3 * Dc) {
        const float* wi = w_ih + tid * Dc;
        const float* wh = w_hh + tid * Dc;
        float g  = b_ih[tid];
        float gh = b_hh[tid];
#pragma unroll
        for (int d = 0; d < Dc; d++) {
            g  = fmaf(agg_sh[d], wi[d], g);
            gh = fmaf(h1_sh[d], wh[d], gh);
        }
        gi_sh[tid] = g;
        gh_sh[tid] = gh;
    }
    __syncthreads();
    if (tid < Dc) {
        const float r = sigmoidf_(gi_sh[tid] + gh_sh[tid]);
        const float z = sigmoidf_(gi_sh[Dc + tid] + gh_sh[Dc + tid]);
        const float n = tanhf(gi_sh[2 * Dc + tid] + r * gh_sh[2 * Dc + tid]);
        out[((size_t)b * Nc + i) * Dc + tid] = (1.0f - z) * n + z * h1_sh[tid];
    }
}

} // namespace

extern "C" void kernel_launch(void* const* d_in, const int* in_sizes, int n_in,
                              void* d_out, int out_size) {
    const float* nodes = (const float*)d_in[0];
    const float* edges = (const float*)d_in[1];
    const float* mask  = (const float*)d_in[2];
    const float* W_agg = (const float*)d_in[3];
    const float* b_agg = (const float*)d_in[4];
    const float* w_ih  = (const float*)d_in[5];
    const float* w_hh  = (const float*)d_in[6];
    const float* b_ih  = (const float*)d_in[7];
    const float* b_hh  = (const float*)d_in[8];
    float* out = (float*)d_out;

    mp_layer_kernel<<<Bc * Nc, THREADS>>>(nodes, edges, mask, W_agg, b_agg,
                                          w_ih, w_hh, b_ih, b_hh, out);
}

// round 2
// speedup vs baseline: 1.0521x; 1.0521x over previous
#include <cuda_runtime.h>
#include <math.h>

namespace {

constexpr int Bc = 32, Nc = 96, Dc = 32, Fc = 16;
constexpr int THREADS = 1024;   // = Dc*Dc, thread tid -> A[p=tid>>5][q=tid&31]

__device__ __forceinline__ float sigmoidf_(float x) { return 1.0f / (1.0f + expf(-x)); }

// Packed f32x2 helpers (Blackwell FFMA2 path — only reachable via PTX).
__device__ __forceinline__ unsigned long long fma2_(unsigned long long a,
                                                    unsigned long long b,
                                                    unsigned long long c) {
    unsigned long long d;
    asm("fma.rn.f32x2 %0, %1, %2, %3;" : "=l"(d) : "l"(a), "l"(b), "l"(c));
    return d;
}
__device__ __forceinline__ unsigned long long add2_(unsigned long long a,
                                                    unsigned long long b) {
    unsigned long long d;
    asm("add.rn.f32x2 %0, %1, %2;" : "=l"(d) : "l"(a), "l"(b));
    return d;
}
__device__ __forceinline__ float hsum2_(unsigned long long v) {
    unsigned lo, hi;
    asm("mov.b64 {%0,%1}, %2;" : "=r"(lo), "=r"(hi) : "l"(v));
    return __uint_as_float(lo) + __uint_as_float(hi);
}

__global__ __launch_bounds__(THREADS, 1)
void mp_layer_kernel(const float* __restrict__ nodes,   // [B, N, D]
                     const float* __restrict__ edges,   // [B, N*N, F]
                     const float* __restrict__ mask,    // [B, N*N, 1] (0/1)
                     const float* __restrict__ W_agg,   // [F, D*D]
                     const float* __restrict__ b_agg,   // [D*D]
                     const float* __restrict__ w_ih,    // [3D, D]
                     const float* __restrict__ w_hh,    // [3D, D]
                     const float* __restrict__ b_ih,    // [3D]
                     const float* __restrict__ b_hh,    // [3D]
                     float* __restrict__ out)           // [B, N, D]
{
    __shared__ __align__(16) float edges_sh[Nc * Fc];   // edge rows for this (b,i)
    __shared__ float mnodes_sh[Nc * Dc];    // nodes[b,j,:] * mask[b, i*N+j]
    __shared__ int   active_sh[Nc];         // compacted list of active j
    __shared__ int   count_sh;
    __shared__ float agg_sh[Dc];
    __shared__ float x1_sh[Dc];
    __shared__ float h1_sh[Dc];
    __shared__ float gi_sh[3 * Dc];
    __shared__ float gh_sh[3 * Dc];

    const int tid  = threadIdx.x;
    const int lane = tid & 31;   // q
    const int p    = tid >> 5;   // p
    const int bi   = blockIdx.x;
    const int b    = bi / Nc;
    const int i    = bi - b * Nc;

    const size_t ebase = ((size_t)b * (Nc * Nc) + (size_t)i * Nc) * Fc;
    const size_t mbase = (size_t)b * (Nc * Nc) + (size_t)i * Nc;
    const size_t nbase = (size_t)b * (Nc * Dc);

    // W_agg column for this thread's (p,q), packed as 8 f-pair b64 registers.
    unsigned long long Wp[Fc / 2];
#pragma unroll
    for (int k = 0; k < Fc / 2; k++) {
        const float wlo = W_agg[(2 * k)     * (Dc * Dc) + tid];
        const float whi = W_agg[(2 * k + 1) * (Dc * Dc) + tid];
        asm("mov.b64 %0, {%1,%2};" : "=l"(Wp[k])
            : "r"(__float_as_uint(wlo)), "r"(__float_as_uint(whi)));
    }
    const float breg = b_agg[tid];

    // Stage edge rows (96 x 16 floats, contiguous) into SMEM via float4.
    {
        const float4* src = reinterpret_cast<const float4*>(edges + ebase);
        float4*       dst = reinterpret_cast<float4*>(edges_sh);
        if (tid < (Nc * Fc) / 4) dst[tid] = src[tid];
    }
    // Mask-premultiplied source nodes: mnodes[j*32+q] = nodes[b,j,q]*mask[b,e(i,j)]
    for (int k = tid; k < Nc * Dc; k += THREADS) {
        const int j = k >> 5;
        mnodes_sh[k] = nodes[nbase + k] * mask[mbase + j];
    }
    // x1 = nodes[b, i, :] (unmasked, GRU input 1)
    if (tid < Dc) x1_sh[tid] = nodes[nbase + (size_t)i * Dc + tid];

    // Warp 0: compact the list of active edges (mask != 0) via ballot prefix.
    if (tid < 32) {
        int cnt = 0;
#pragma unroll
        for (int r = 0; r < Nc / 32; r++) {
            const int j = r * 32 + lane;
            const bool a = (mask[mbase + j] != 0.0f);
            const unsigned bal = __ballot_sync(0xffffffffu, a);
            if (a) {
                const int pos = cnt + __popc(bal & ((1u << lane) - 1u));
                active_sh[pos] = j;
            }
            cnt += __popc(bal);
        }
        if (lane == 0) count_sh = cnt;
    }
    __syncthreads();

    // Main loop: only active edges. Unrolled x2 with split chains for ILP.
    const int cnt = count_sh;
    float acc0 = 0.0f, acc1 = 0.0f;
    const ulonglong2* eview = reinterpret_cast<const ulonglong2*>(edges_sh);

    int a = 0;
    for (; a + 2 <= cnt; a += 2) {
        const int j0 = active_sh[a];
        const int j1 = active_sh[a + 1];
        // Hoist all loads (broadcast LDS.128 for edges, per-lane LDS.32 mnode).
        const ulonglong2 x0 = eview[j0 * 4 + 0];
        const ulonglong2 x1 = eview[j0 * 4 + 1];
        const ulonglong2 x2 = eview[j0 * 4 + 2];
        const ulonglong2 x3 = eview[j0 * 4 + 3];
        const ulonglong2 y0 = eview[j1 * 4 + 0];
        const ulonglong2 y1 = eview[j1 * 4 + 1];
        const ulonglong2 y2 = eview[j1 * 4 + 2];
        const ulonglong2 y3 = eview[j1 * 4 + 3];
        const float mn0 = mnodes_sh[j0 * Dc + lane];
        const float mn1 = mnodes_sh[j1 * Dc + lane];

        // Edge j0: two 4-deep packed chains.
        unsigned long long cA = fma2_(x0.x, Wp[0], 0ull);
        unsigned long long cB = fma2_(x2.x, Wp[4], 0ull);
        // Edge j1: two more independent chains.
        unsigned long long dA = fma2_(y0.x, Wp[0], 0ull);
        unsigned long long dB = fma2_(y2.x, Wp[4], 0ull);

        cA = fma2_(x0.y, Wp[1], cA);  cB = fma2_(x2.y, Wp[5], cB);
        dA = fma2_(y0.y, Wp[1], dA);  dB = fma2_(y2.y, Wp[5], dB);
        cA = fma2_(x1.x, Wp[2], cA);  cB = fma2_(x3.x, Wp[6], cB);
        dA = fma2_(y1.x, Wp[2], dA);  dB = fma2_(y3.x, Wp[6], dB);
        cA = fma2_(x1.y, Wp[3], cA);  cB = fma2_(x3.y, Wp[7], cB);
        dA = fma2_(y1.y, Wp[3], dA);  dB = fma2_(y3.y, Wp[7], dB);

        const float s0 = fmaxf(breg + hsum2_(add2_(cA, cB)), 0.0f);
        const float s1 = fmaxf(breg + hsum2_(add2_(dA, dB)), 0.0f);
        acc0 = fmaf(s0, mn0, acc0);
        acc1 = fmaf(s1, mn1, acc1);
    }
    if (a < cnt) {   // tail edge
        const int j0 = active_sh[a];
        const ulonglong2 x0 = eview[j0 * 4 + 0];
        const ulonglong2 x1 = eview[j0 * 4 + 1];
        const ulonglong2 x2 = eview[j0 * 4 + 2];
        const ulonglong2 x3 = eview[j0 * 4 + 3];
        const float mn0 = mnodes_sh[j0 * Dc + lane];
        unsigned long long cA = fma2_(x0.x, Wp[0], 0ull);
        unsigned long long cB = fma2_(x2.x, Wp[4], 0ull);
        cA = fma2_(x0.y, Wp[1], cA);  cB = fma2_(x2.y, Wp[5], cB);
        cA = fma2_(x1.x, Wp[2], cA);  cB = fma2_(x3.x, Wp[6], cB);
        cA = fma2_(x1.y, Wp[3], cA);  cB = fma2_(x3.y, Wp[7], cB);
        const float s0 = fmaxf(breg + hsum2_(add2_(cA, cB)), 0.0f);
        acc0 = fmaf(s0, mn0, acc0);
    }

    // Reduce over q (lanes) -> message/agg component p.
    float acc = acc0 + acc1;
#pragma unroll
    for (int o = 16; o; o >>= 1) acc += __shfl_xor_sync(0xffffffffu, acc, o);
    if (lane == 0) agg_sh[p] = acc;
    __syncthreads();

    // ---- GRU combiner (row (b,i)), h0 = 0 ----
    // Step 1: x = nodes[b,i,:], h = 0  =>  gh = b_hh
    if (tid < 3 * Dc) {
        const float* wrow = w_ih + tid * Dc;
        float g = b_ih[tid];
#pragma unroll
        for (int d = 0; d < Dc; d++) g = fmaf(x1_sh[d], wrow[d], g);
        gi_sh[tid] = g;
    }
    __syncthreads();
    if (tid < Dc) {
        const float r = sigmoidf_(gi_sh[tid] + b_hh[tid]);
        const float z = sigmoidf_(gi_sh[Dc + tid] + b_hh[Dc + tid]);
        const float n = tanhf(gi_sh[2 * Dc + tid] + r * b_hh[2 * Dc + tid]);
        h1_sh[tid] = (1.0f - z) * n;   // + z*h0, h0 = 0
    }
    __syncthreads();
    // Step 2: x = agg, h = h1
    if (tid < 3 * Dc) {
        const float* wi = w_ih + tid * Dc;
        const float* wh = w_hh + tid * Dc;
        float g  = b_ih[tid];
        float gh = b_hh[tid];
#pragma unroll
        for (int d = 0; d < Dc; d++) {
            g  = fmaf(agg_sh[d], wi[d], g);
            gh = fmaf(h1_sh[d], wh[d], gh);
        }
        gi_sh[tid] = g;
        gh_sh[tid] = gh;
    }
    __syncthreads();
    if (tid < Dc) {
        const float r = sigmoidf_(gi_sh[tid] + gh_sh[tid]);
        const float z = sigmoidf_(gi_sh[Dc + tid] + gh_sh[Dc + tid]);
        const float n = tanhf(gi_sh[2 * Dc + tid] + r * gh_sh[2 * Dc + tid]);
        out[((size_t)b * Nc + i) * Dc + tid] = (1.0f - z) * n + z * h1_sh[tid];
    }
}

} // namespace

extern "C" void kernel_launch(void* const* d_in, const int* in_sizes, int n_in,
                              void* d_out, int out_size) {
    const float* nodes = (const float*)d_in[0];
    const float* edges = (const float*)d_in[1];
    const float* mask  = (const float*)d_in[2];
    const float* W_agg = (const float*)d_in[3];
    const float* b_agg = (const float*)d_in[4];
    const float* w_ih  = (const float*)d_in[5];
    const float* w_hh  = (const float*)d_in[6];
    const float* b_ih  = (const float*)d_in[7];
    const float* b_hh  = (const float*)d_in[8];
    float* out = (float*)d_out;

    mp_layer_kernel<<<Bc * Nc, THREADS>>>(nodes, edges, mask, W_agg, b_agg,
                                          w_ih, w_hh, b_ih, b_hh, out);
}

// round 3
// speedup vs baseline: 1.4303x; 1.3595x over previous
#include <cuda_runtime.h>
#include <math.h>

namespace {

constexpr int Bc = 32, Nc = 96, Dc = 32, Fc = 16;
constexpr int THREADS = 256;   // 8 warps; warp w owns p-rows {w, w+8, w+16, w+24}
constexpr int PROWS = 4;

__device__ __forceinline__ float sigmoidf_(float x) { return 1.0f / (1.0f + expf(-x)); }

// Packed f32x2 helpers (Blackwell FFMA2 path — only reachable via PTX).
__device__ __forceinline__ unsigned long long fma2_(unsigned long long a,
                                                    unsigned long long b,
                                                    unsigned long long c) {
    unsigned long long d;
    asm("fma.rn.f32x2 %0, %1, %2, %3;" : "=l"(d) : "l"(a), "l"(b), "l"(c));
    return d;
}
__device__ __forceinline__ unsigned long long add2_(unsigned long long a,
                                                    unsigned long long b) {
    unsigned long long d;
    asm("add.rn.f32x2 %0, %1, %2;" : "=l"(d) : "l"(a), "l"(b));
    return d;
}
__device__ __forceinline__ float hsum2_(unsigned long long v) {
    unsigned lo, hi;
    asm("mov.b64 {%0,%1}, %2;" : "=r"(lo), "=r"(hi) : "l"(v));
    return __uint_as_float(lo) + __uint_as_float(hi);
}
__device__ __forceinline__ unsigned long long pack2_(float lo, float hi) {
    unsigned long long d;
    asm("mov.b64 %0, {%1,%2};" : "=l"(d)
        : "r"(__float_as_uint(lo)), "r"(__float_as_uint(hi)));
    return d;
}

__global__ __launch_bounds__(THREADS, 2)
void mp_layer_kernel(const float* __restrict__ nodes,   // [B, N, D]
                     const float* __restrict__ edges,   // [B, N*N, F]
                     const float* __restrict__ mask,    // [B, N*N, 1] (0/1)
                     const float* __restrict__ W_agg,   // [F, D*D]
                     const float* __restrict__ b_agg,   // [D*D]
                     const float* __restrict__ w_ih,    // [3D, D]
                     const float* __restrict__ w_hh,    // [3D, D]
                     const float* __restrict__ b_ih,    // [3D]
                     const float* __restrict__ b_hh,    // [3D]
                     float* __restrict__ out)           // [B, N, D]
{
    __shared__ __align__(16) float edges_sh[Nc * Fc];   // edge rows for this (b,i)
    __shared__ __align__(16) float mnodes_sh[Nc * Dc];  // nodes[b,j,:] * mask
    __shared__ int   active_sh[Nc];
    __shared__ int   count_sh;
    __shared__ float agg_sh[Dc];
    __shared__ float x1_sh[Dc];
    __shared__ float h1_sh[Dc];
    __shared__ float gi_sh[3 * Dc];
    __shared__ float gh_sh[3 * Dc];

    const int tid  = threadIdx.x;
    const int lane = tid & 31;   // q
    const int w    = tid >> 5;   // warp id -> base p
    const int bi   = blockIdx.x;
    const int b    = bi / Nc;
    const int i    = bi - b * Nc;

    const size_t ebase = ((size_t)b * (Nc * Nc) + (size_t)i * Nc) * Fc;
    const size_t mbase = (size_t)b * (Nc * Nc) + (size_t)i * Nc;
    const size_t nbase = (size_t)b * (Nc * Dc);

    // W columns for this thread's 4 (p,q) entries, packed over f-pairs.
    unsigned long long Wp[PROWS][Fc / 2];
    unsigned long long bpack[PROWS];
#pragma unroll
    for (int r = 0; r < PROWS; r++) {
        const int col = (w + 8 * r) * Dc + lane;
#pragma unroll
        for (int k = 0; k < Fc / 2; k++)
            Wp[r][k] = pack2_(W_agg[(2 * k) * (Dc * Dc) + col],
                              W_agg[(2 * k + 1) * (Dc * Dc) + col]);
        bpack[r] = pack2_(b_agg[col], 0.0f);   // bias seeds the lo-lane chain
    }

    // Stage edge rows (96 x 16 floats) into SMEM via float4.
    {
        const float4* src = reinterpret_cast<const float4*>(edges + ebase);
        float4*       dst = reinterpret_cast<float4*>(edges_sh);
        for (int k = tid; k < (Nc * Fc) / 4; k += THREADS) dst[k] = src[k];
    }
    // Mask-premultiplied source nodes (vectorized): 96 rows x 8 float4.
    {
        const float4* src = reinterpret_cast<const float4*>(nodes + nbase);
        float4*       dst = reinterpret_cast<float4*>(mnodes_sh);
        for (int k = tid; k < (Nc * Dc) / 4; k += THREADS) {
            const int j = k >> 3;
            const float m = mask[mbase + j];
            float4 v = src[k];
            v.x *= m; v.y *= m; v.z *= m; v.w *= m;
            dst[k] = v;
        }
    }
    if (tid < Dc) x1_sh[tid] = nodes[nbase + (size_t)i * Dc + tid];

    // Warp 0: compact active edges (mask != 0) via ballot prefix.
    if (tid < 32) {
        int cnt = 0;
#pragma unroll
        for (int rr = 0; rr < Nc / 32; rr++) {
            const int j = rr * 32 + lane;
            const bool act = (mask[mbase + j] != 0.0f);
            const unsigned bal = __ballot_sync(0xffffffffu, act);
            if (act) active_sh[cnt + __popc(bal & ((1u << lane) - 1u))] = j;
            cnt += __popc(bal);
        }
        if (lane == 0) count_sh = cnt;
    }
    __syncthreads();

    // Main loop: each LDS'd edge row feeds 4 p-rows (8 indep. FMA chains).
    const int cnt = count_sh;
    float acc[PROWS] = {0.0f, 0.0f, 0.0f, 0.0f};
    const ulonglong2* eview = reinterpret_cast<const ulonglong2*>(edges_sh);

    for (int a = 0; a < cnt; a++) {
        const int j = active_sh[a];
        const ulonglong2 x0 = eview[j * 4 + 0];
        const ulonglong2 x1 = eview[j * 4 + 1];
        const ulonglong2 x2 = eview[j * 4 + 2];
        const ulonglong2 x3 = eview[j * 4 + 3];
        const float mn = mnodes_sh[j * Dc + lane];
#pragma unroll
        for (int r = 0; r < PROWS; r++) {
            unsigned long long cA = fma2_(x0.x, Wp[r][0], bpack[r]);
            unsigned long long cB = fma2_(x2.x, Wp[r][4], 0ull);
            cA = fma2_(x0.y, Wp[r][1], cA);  cB = fma2_(x2.y, Wp[r][5], cB);
            cA = fma2_(x1.x, Wp[r][2], cA);  cB = fma2_(x3.x, Wp[r][6], cB);
            cA = fma2_(x1.y, Wp[r][3], cA);  cB = fma2_(x3.y, Wp[r][7], cB);
            const float s = fmaxf(hsum2_(add2_(cA, cB)), 0.0f);   // ReLU(A[p][q])
            acc[r] = fmaf(s, mn, acc[r]);
        }
    }

    // Reduce each acc[r] over lanes (q) -> agg component p = w + 8r.
#pragma unroll
    for (int r = 0; r < PROWS; r++) {
        float v = acc[r];
#pragma unroll
        for (int o = 16; o; o >>= 1) v += __shfl_xor_sync(0xffffffffu, v, o);
        if (lane == 0) agg_sh[w + 8 * r] = v;
    }
    __syncthreads();

    // ---- GRU combiner (row (b,i)), h0 = 0 ----
    if (tid < 3 * Dc) {
        const float* wrow = w_ih + tid * Dc;
        float g = b_ih[tid];
#pragma unroll
        for (int d = 0; d < Dc; d++) g = fmaf(x1_sh[d], wrow[d], g);
        gi_sh[tid] = g;
    }
    __syncthreads();
    if (tid < Dc) {
        const float r = sigmoidf_(gi_sh[tid] + b_hh[tid]);
        const float z = sigmoidf_(gi_sh[Dc + tid] + b_hh[Dc + tid]);
        const float n = tanhf(gi_sh[2 * Dc + tid] + r * b_hh[2 * Dc + tid]);
        h1_sh[tid] = (1.0f - z) * n;   // + z*h0, h0 = 0
    }
    __syncthreads();
    if (tid < 3 * Dc) {
        const float* wi = w_ih + tid * Dc;
        const float* wh = w_hh + tid * Dc;
        float g  = b_ih[tid];
        float gh = b_hh[tid];
#pragma unroll
        for (int d = 0; d < Dc; d++) {
            g  = fmaf(agg_sh[d], wi[d], g);
            gh = fmaf(h1_sh[d], wh[d], gh);
        }
        gi_sh[tid] = g;
        gh_sh[tid] = gh;
    }
    __syncthreads();
    if (tid < Dc) {
        const float r = sigmoidf_(gi_sh[tid] + gh_sh[tid]);
        const float z = sigmoidf_(gi_sh[Dc + tid] + gh_sh[Dc + tid]);
        const float n = tanhf(gi_sh[2 * Dc + tid] + r * gh_sh[2 * Dc + tid]);
        out[((size_t)b * Nc + i) * Dc + tid] = (1.0f - z) * n + z * h1_sh[tid];
    }
}

} // namespace

extern "C" void kernel_launch(void* const* d_in, const int* in_sizes, int n_in,
                              void* d_out, int out_size) {
    const float* nodes = (const float*)d_in[0];
    const float* edges = (const float*)d_in[1];
    const float* mask  = (const float*)d_in[2];
    const float* W_agg = (const float*)d_in[3];
    const float* b_agg = (const float*)d_in[4];
    const float* w_ih  = (const float*)d_in[5];
    const float* w_hh  = (const float*)d_in[6];
    const float* b_ih  = (const float*)d_in[7];
    const float* b_hh  = (const float*)d_in[8];
    float* out = (float*)d_out;

    mp_layer_kernel<<<Bc * Nc, THREADS>>>(nodes, edges, mask, W_agg, b_agg,
                                          w_ih, w_hh, b_ih, b_hh, out);
}

// round 4
// speedup vs baseline: 1.4382x; 1.0055x over previous
#include <cuda_runtime.h>
#include <math.h>

namespace {

constexpr int Bc = 32, Nc = 96, Dc = 32, Fc = 16;
constexpr int THREADS = 256;   // 8 warps; warp w owns p-rows {w, w+8, w+16, w+24}
constexpr int PROWS = 4;

__device__ __forceinline__ float sigmoidf_(float x) { return 1.0f / (1.0f + expf(-x)); }

__device__ __forceinline__ unsigned long long fma2_(unsigned long long a,
                                                    unsigned long long b,
                                                    unsigned long long c) {
    unsigned long long d;
    asm("fma.rn.f32x2 %0, %1, %2, %3;" : "=l"(d) : "l"(a), "l"(b), "l"(c));
    return d;
}
__device__ __forceinline__ unsigned long long add2_(unsigned long long a,
                                                    unsigned long long b) {
    unsigned long long d;
    asm("add.rn.f32x2 %0, %1, %2;" : "=l"(d) : "l"(a), "l"(b));
    return d;
}
__device__ __forceinline__ float hsum2_(unsigned long long v) {
    unsigned lo, hi;
    asm("mov.b64 {%0,%1}, %2;" : "=r"(lo), "=r"(hi) : "l"(v));
    return __uint_as_float(lo) + __uint_as_float(hi);
}
__device__ __forceinline__ unsigned long long pack2_(float lo, float hi) {
    unsigned long long d;
    asm("mov.b64 %0, {%1,%2};" : "=l"(d)
        : "r"(__float_as_uint(lo)), "r"(__float_as_uint(hi)));
    return d;
}

__global__ __launch_bounds__(THREADS, 2)
void mp_layer_kernel(const float* __restrict__ nodes,   // [B, N, D]
                     const float* __restrict__ edges,   // [B, N*N, F]
                     const float* __restrict__ mask,    // [B, N*N, 1] (0/1)
                     const float* __restrict__ W_agg,   // [F, D*D]
                     const float* __restrict__ b_agg,   // [D*D]
                     const float* __restrict__ w_ih,    // [3D, D]
                     const float* __restrict__ w_hh,    // [3D, D]
                     const float* __restrict__ b_ih,    // [3D]
                     const float* __restrict__ b_hh,    // [3D]
                     float* __restrict__ out)           // [B, N, D]
{
    __shared__ __align__(16) float edges_sh[Nc * Fc];
    __shared__ __align__(16) float mnodes_sh[Nc * Dc];
    __shared__ int   active_sh[Nc];
    __shared__ int   count_sh;
    __shared__ float agg_sh[Dc];
    __shared__ float x1_sh[Dc];
    __shared__ float h1_sh[Dc];
    __shared__ float gi_sh[3 * Dc];
    __shared__ float gh_sh[3 * Dc];

    const int tid  = threadIdx.x;
    const int lane = tid & 31;   // q
    const int w    = tid >> 5;   // warp id -> base p
    const int bi   = blockIdx.x;
    const int b    = bi / Nc;
    const int i    = bi - b * Nc;

    const size_t ebase = ((size_t)b * (Nc * Nc) + (size_t)i * Nc) * Fc;
    const size_t mbase = (size_t)b * (Nc * Nc) + (size_t)i * Nc;
    const size_t nbase = (size_t)b * (Nc * Dc);

    // W columns for this thread's 4 (p,q) entries, packed over f-pairs.
    unsigned long long Wp[PROWS][Fc / 2];
    float breg[PROWS];
#pragma unroll
    for (int r = 0; r < PROWS; r++) {
        const int col = (w + 8 * r) * Dc + lane;
#pragma unroll
        for (int k = 0; k < Fc / 2; k++)
            Wp[r][k] = pack2_(W_agg[(2 * k) * (Dc * Dc) + col],
                              W_agg[(2 * k + 1) * (Dc * Dc) + col]);
        breg[r] = b_agg[col];
    }

    // Stage edge rows (96 x 16 floats) into SMEM via float4.
    {
        const float4* src = reinterpret_cast<const float4*>(edges + ebase);
        float4*       dst = reinterpret_cast<float4*>(edges_sh);
        for (int k = tid; k < (Nc * Fc) / 4; k += THREADS) dst[k] = src[k];
    }
    // Mask-premultiplied source nodes (vectorized).
    {
        const float4* src = reinterpret_cast<const float4*>(nodes + nbase);
        float4*       dst = reinterpret_cast<float4*>(mnodes_sh);
        for (int k = tid; k < (Nc * Dc) / 4; k += THREADS) {
            const int j = k >> 3;
            const float m = mask[mbase + j];
            float4 v = src[k];
            v.x *= m; v.y *= m; v.z *= m; v.w *= m;
            dst[k] = v;
        }
    }
    if (tid < Dc) x1_sh[tid] = nodes[nbase + (size_t)i * Dc + tid];

    // Warp 0: compact active edges (mask != 0) via ballot prefix.
    if (tid < 32) {
        int cnt = 0;
#pragma unroll
        for (int rr = 0; rr < Nc / 32; rr++) {
            const int j = rr * 32 + lane;
            const bool act = (mask[mbase + j] != 0.0f);
            const unsigned bal = __ballot_sync(0xffffffffu, act);
            if (act) active_sh[cnt + __popc(bal & ((1u << lane) - 1u))] = j;
            cnt += __popc(bal);
        }
        if (lane == 0) count_sh = cnt;
    }
    __syncthreads();

    const int cnt = count_sh;
    float acc[PROWS] = {0.0f, 0.0f, 0.0f, 0.0f};
    const ulonglong2* eview = reinterpret_cast<const ulonglong2*>(edges_sh);

    // Double-buffered, software-pipelined edge loop: loads for edge a+1
    // issue before the FMA block of edge a, hiding the 29-cyc LDS latency.
    ulonglong2 A0, A1, A2, A3, B0, B1, B2, B3;
    float mnA, mnB;

#define LOAD_A(J) { const int _j = (J); A0 = eview[_j*4+0]; A1 = eview[_j*4+1]; \
                    A2 = eview[_j*4+2]; A3 = eview[_j*4+3]; \
                    mnA = mnodes_sh[_j*Dc + lane]; }
#define LOAD_B(J) { const int _j = (J); B0 = eview[_j*4+0]; B1 = eview[_j*4+1]; \
                    B2 = eview[_j*4+2]; B3 = eview[_j*4+3]; \
                    mnB = mnodes_sh[_j*Dc + lane]; }
#define COMPUTE(X0, X1, X2, X3, MN) { \
    _Pragma("unroll") \
    for (int r = 0; r < PROWS; r++) { \
        unsigned long long cA = fma2_(X0.x, Wp[r][0], 0ull); \
        unsigned long long cB = fma2_(X2.x, Wp[r][4], 0ull); \
        cA = fma2_(X0.y, Wp[r][1], cA);  cB = fma2_(X2.y, Wp[r][5], cB); \
        cA = fma2_(X1.x, Wp[r][2], cA);  cB = fma2_(X3.x, Wp[r][6], cB); \
        cA = fma2_(X1.y, Wp[r][3], cA);  cB = fma2_(X3.y, Wp[r][7], cB); \
        const float s = fmaxf(breg[r] + hsum2_(add2_(cA, cB)), 0.0f); \
        acc[r] = fmaf(s, MN, acc[r]); \
    } }

    if (cnt > 0) {
        LOAD_A(active_sh[0]);
        int a = 0;
        for (; a + 2 <= cnt; a += 2) {
            LOAD_B(active_sh[a + 1]);
            COMPUTE(A0, A1, A2, A3, mnA);
            LOAD_A(active_sh[(a + 2 < cnt) ? a + 2 : a + 1]);  // dummy-safe
            COMPUTE(B0, B1, B2, B3, mnB);
        }
        if (a < cnt) COMPUTE(A0, A1, A2, A3, mnA);
    }
#undef LOAD_A
#undef LOAD_B
#undef COMPUTE

    // Reduce each acc[r] over lanes (q) -> agg component p = w + 8r.
#pragma unroll
    for (int r = 0; r < PROWS; r++) {
        float v = acc[r];
#pragma unroll
        for (int o = 16; o; o >>= 1) v += __shfl_xor_sync(0xffffffffu, v, o);
        if (lane == 0) agg_sh[w + 8 * r] = v;
    }
    __syncthreads();

    // ---- GRU combiner (row (b,i)), h0 = 0 ----
    if (tid < 3 * Dc) {
        const float* wrow = w_ih + tid * Dc;
        float g = b_ih[tid];
#pragma unroll
        for (int d = 0; d < Dc; d++) g = fmaf(x1_sh[d], wrow[d], g);
        gi_sh[tid] = g;
    }
    __syncthreads();
    if (tid < Dc) {
        const float r = sigmoidf_(gi_sh[tid] + b_hh[tid]);
        const float z = sigmoidf_(gi_sh[Dc + tid] + b_hh[Dc + tid]);
        const float n = tanhf(gi_sh[2 * Dc + tid] + r * b_hh[2 * Dc + tid]);
        h1_sh[tid] = (1.0f - z) * n;   // + z*h0, h0 = 0
    }
    __syncthreads();
    if (tid < 3 * Dc) {
        const float* wi = w_ih + tid * Dc;
        const float* wh = w_hh + tid * Dc;
        float g  = b_ih[tid];
        float gh = b_hh[tid];
#pragma unroll
        for (int d = 0; d < Dc; d++) {
            g  = fmaf(agg_sh[d], wi[d], g);
            gh = fmaf(h1_sh[d], wh[d], gh);
        }
        gi_sh[tid] = g;
        gh_sh[tid] = gh;
    }
    __syncthreads();
    if (tid < Dc) {
        const float r = sigmoidf_(gi_sh[tid] + gh_sh[tid]);
        const float z = sigmoidf_(gi_sh[Dc + tid] + gh_sh[Dc + tid]);
        const float n = tanhf(gi_sh[2 * Dc + tid] + r * gh_sh[2 * Dc + tid]);
        out[((size_t)b * Nc + i) * Dc + tid] = (1.0f - z) * n + z * h1_sh[tid];
    }
}

} // namespace

extern "C" void kernel_launch(void* const* d_in, const int* in_sizes, int n_in,
                              void* d_out, int out_size) {
    const float* nodes = (const float*)d_in[0];
    const float* edges = (const float*)d_in[1];
    const float* mask  = (const float*)d_in[2];
    const float* W_agg = (const float*)d_in[3];
    const float* b_agg = (const float*)d_in[4];
    const float* w_ih  = (const float*)d_in[5];
    const float* w_hh  = (const float*)d_in[6];
    const float* b_ih  = (const float*)d_in[7];
    const float* b_hh  = (const float*)d_in[8];
    float* out = (float*)d_out;

    mp_layer_kernel<<<Bc * Nc, THREADS>>>(nodes, edges, mask, W_agg, b_agg,
                                          w_ih, w_hh, b_ih, b_hh, out);
}

// round 6
// speedup vs baseline: 1.5641x; 1.0875x over previous
#include <cuda_runtime.h>
#include <math.h>
#include <stdint.h>

namespace {

constexpr int Bc = 32, Nc = 96, Dc = 32, Fc = 16;
constexpr int THREADS = 256;        // 8 warps; warp w owns output cols [w*128, w*128+128)
constexpr int GRID    = 304;        // persistent: 2 CTAs per SM on 152-SM GB300
constexpr int NTILES  = Bc * Nc;    // 3072 (b,i) tiles
constexpr int EPAD    = 20;         // E_act row pad (stride-20 -> conflict-free quads)

// SMEM byte offsets
constexpr int OFF_WFRAG = 0;                 // 128 ntile x 2 ks x 32 lane float2 = 65536
constexpr int OFF_BIAS  = 65536;             // 1024 float = 4096
constexpr int OFF_E     = 69632;             // 96 x 20 u32 (tf32 bits) = 7680
constexpr int OFF_MN    = 77312;             // 1536 float2 = 12288
constexpr int OFF_ACT   = 89600;             // 96 int
constexpr int OFF_CNT   = 89984;             // int
constexpr int OFF_AGG   = 90000;             // 32 f
constexpr int OFF_X1    = 90128;             // 32 f
constexpr int OFF_H1    = 90256;             // 32 f
constexpr int OFF_GI    = 90384;             // 96 f
constexpr int OFF_GH    = 90768;             // 96 f
constexpr int SMEM_BYTES = 91200;

__device__ __forceinline__ float sigmoidf_(float x) { return 1.0f / (1.0f + expf(-x)); }

__device__ __forceinline__ uint32_t f2tf32(float x) {
    uint32_t r;
    asm("cvt.rna.tf32.f32 %0, %1;" : "=r"(r) : "f"(x));
    return r;
}

__device__ __forceinline__ void mma_tf32(float& d0, float& d1, float& d2, float& d3,
                                         uint32_t a0, uint32_t a1, uint32_t a2, uint32_t a3,
                                         uint32_t b0, uint32_t b1) {
    asm volatile(
        "mma.sync.aligned.m16n8k8.row.col.f32.tf32.tf32.f32 "
        "{%0,%1,%2,%3}, {%4,%5,%6,%7}, {%8,%9}, {%0,%1,%2,%3};"
        : "+f"(d0), "+f"(d1), "+f"(d2), "+f"(d3)
        : "r"(a0), "r"(a1), "r"(a2), "r"(a3), "r"(b0), "r"(b1));
}

// mn storage index: (e, qp) -> float2 slot.
// Block = (qp>>2)*12 + (e>>3); within-block slot = (qp&3)*8 + (e&7)  [32 slots,
// bijective]. Epilogue read (fixed t, lanes vary l4=qp&3, lr=e&7) touches all
// 32 slots of one block exactly once -> conflict-free LDS.64.
__device__ __forceinline__ int mn_idx(int e, int qp) {
    return (((qp >> 2) * 12 + (e >> 3)) << 5) + ((qp & 3) << 3) + (e & 7);
}

__global__ __launch_bounds__(THREADS, 2)
void mp_layer_kernel(const float* __restrict__ nodes,   // [B, N, D]
                     const float* __restrict__ edges,   // [B, N*N, F]
                     const float* __restrict__ mask,    // [B, N*N, 1] (0/1)
                     const float* __restrict__ W_agg,   // [F, D*D]
                     const float* __restrict__ b_agg,   // [D*D]
                     const float* __restrict__ w_ih,    // [3D, D]
                     const float* __restrict__ w_hh,    // [3D, D]
                     const float* __restrict__ b_ih,    // [3D]
                     const float* __restrict__ b_hh,    // [3D]
                     float* __restrict__ out)           // [B, N, D]
{
    extern __shared__ char smem[];
    float2*   wfrag    = reinterpret_cast<float2*>(smem + OFF_WFRAG);
    float*    bias_sh  = reinterpret_cast<float*>(smem + OFF_BIAS);
    uint32_t* E_sh     = reinterpret_cast<uint32_t*>(smem + OFF_E);
    float2*   mnS      = reinterpret_cast<float2*>(smem + OFF_MN);
    int*      active_sh= reinterpret_cast<int*>(smem + OFF_ACT);
    int*      count_sh = reinterpret_cast<int*>(smem + OFF_CNT);
    float*    agg_sh   = reinterpret_cast<float*>(smem + OFF_AGG);
    float*    x1_sh    = reinterpret_cast<float*>(smem + OFF_X1);
    float*    h1_sh    = reinterpret_cast<float*>(smem + OFF_H1);
    float*    gi_sh    = reinterpret_cast<float*>(smem + OFF_GI);
    float*    gh_sh    = reinterpret_cast<float*>(smem + OFF_GH);

    const int tid  = threadIdx.x;
    const int lane = tid & 31;
    const int w    = tid >> 5;

    // ---- One-time per CTA: stage W fragments (tf32) + bias ----
    // wfrag[(nt*2 + ks)*32 + lane] = {W[k, col], W[k+4, col]},
    //   col = nt*8 + lane/4, k = ks*8 + lane%4  (mma B-frag layout, row.col)
    for (int idx = tid; idx < 128 * 2 * 32; idx += THREADS) {
        const int l  = idx & 31;
        const int ks = (idx >> 5) & 1;
        const int nt = idx >> 6;
        const int col = nt * 8 + (l >> 2);
        const int k0  = ks * 8 + (l & 3);
        float2 v;
        v.x = __uint_as_float(f2tf32(W_agg[k0 * 1024 + col]));
        v.y = __uint_as_float(f2tf32(W_agg[(k0 + 4) * 1024 + col]));
        wfrag[idx] = v;
    }
    for (int c = tid; c < 1024; c += THREADS) bias_sh[c] = b_agg[c];

    // ---- Persistent tile loop ----
    for (int tile = blockIdx.x; tile < NTILES; tile += GRID) {
        const int b = tile / Nc;
        const int i = tile - b * Nc;
        const size_t ebase = ((size_t)b * (Nc * Nc) + (size_t)i * Nc) * Fc;
        const size_t mbase = (size_t)b * (Nc * Nc) + (size_t)i * Nc;
        const size_t nbase = (size_t)b * (Nc * Dc);

        __syncthreads();   // previous tile fully consumed

        // Warp 0: compact active edges. Warp 1: stage x1.
        if (tid < 32) {
            int cnt = 0;
#pragma unroll
            for (int rr = 0; rr < Nc / 32; rr++) {
                const int j = rr * 32 + lane;
                const bool act = (mask[mbase + j] != 0.0f);
                const unsigned bal = __ballot_sync(0xffffffffu, act);
                if (act) active_sh[cnt + __popc(bal & ((1u << lane) - 1u))] = j;
                cnt += __popc(bal);
            }
            if (lane == 0) count_sh[0] = cnt;
        } else if (tid >= 32 && tid < 64) {
            x1_sh[lane] = nodes[nbase + (size_t)i * Dc + lane];
        }
        __syncthreads();

        const int cnt    = count_sh[0];
        const int mtiles = (cnt + 15) >> 4;
        const int padcnt = mtiles << 4;

        // Stage E_act (tf32 bits, rows padded with 0) and mn (padded with 0).
        for (int idx = tid; idx < padcnt * Fc; idx += THREADS) {
            const int a = idx >> 4;
            const int f = idx & 15;
            uint32_t v = 0u;
            if (a < cnt) v = f2tf32(edges[ebase + (size_t)active_sh[a] * Fc + f]);
            E_sh[a * EPAD + f] = v;
        }
        for (int idx = tid; idx < padcnt * 16; idx += THREADS) {
            const int a  = idx >> 4;
            const int qp = idx & 15;
            float2 v = make_float2(0.0f, 0.0f);
            if (a < cnt) {
                const float* src = nodes + nbase + (size_t)active_sh[a] * Dc + qp * 2;
                v = *reinterpret_cast<const float2*>(src);
            }
            mnS[mn_idx(a, qp)] = v;
        }
        __syncthreads();

        // ---- MMA + fused epilogue ----
        float acc0 = 0.0f, acc1 = 0.0f, acc2 = 0.0f, acc3 = 0.0f;
        const int l4  = lane & 3;
        const int lr  = lane >> 2;

        for (int mt = 0; mt < mtiles; mt++) {
            const int r0 = mt * 16 + lr;
            const uint32_t* e0p = E_sh + r0 * EPAD;
            const uint32_t* e1p = E_sh + (r0 + 8) * EPAD;
            // A fragments for both k-steps (held across the 16 n-tiles).
            const uint32_t a00 = e0p[l4],     a01 = e1p[l4];
            const uint32_t a02 = e0p[l4 + 4], a03 = e1p[l4 + 4];
            const uint32_t a10 = e0p[l4 + 8], a11 = e1p[l4 + 8];
            const uint32_t a12 = e0p[l4 + 12],a13 = e1p[l4 + 12];

#pragma unroll
            for (int t = 0; t < 16; t++) {
                const int ntb = (w * 16 + t) * 2;
                const float2 bf0 = wfrag[(ntb)     * 32 + lane];
                const float2 bf1 = wfrag[(ntb + 1) * 32 + lane];

                float d0 = 0.0f, d1 = 0.0f, d2 = 0.0f, d3 = 0.0f;
                mma_tf32(d0, d1, d2, d3, a00, a01, a02, a03,
                         __float_as_uint(bf0.x), __float_as_uint(bf0.y));
                mma_tf32(d0, d1, d2, d3, a10, a11, a12, a13,
                         __float_as_uint(bf1.x), __float_as_uint(bf1.y));

                const float2 bb = *reinterpret_cast<const float2*>(
                    bias_sh + w * 128 + t * 8 + l4 * 2);
                d0 = fmaxf(d0 + bb.x, 0.0f);
                d1 = fmaxf(d1 + bb.y, 0.0f);
                d2 = fmaxf(d2 + bb.x, 0.0f);
                d3 = fmaxf(d3 + bb.y, 0.0f);

                const int qp = (t & 3) * 4 + l4;
                const float2 m0 = mnS[mn_idx(r0, qp)];
                const float2 m1 = mnS[mn_idx(r0 + 8, qp)];
                const float c = fmaf(d0, m0.x, fmaf(d1, m0.y,
                                fmaf(d2, m1.x, d3 * m1.y)));
                // p-group for this n-tile: t>>2
                if ((t >> 2) == 0) acc0 += c;
                else if ((t >> 2) == 1) acc1 += c;
                else if ((t >> 2) == 2) acc2 += c;
                else acc3 += c;
            }
        }

        // Warp-reduce the 4 p-accumulators -> agg_sh[w*4 + pi]
        float av[4] = {acc0, acc1, acc2, acc3};
#pragma unroll
        for (int pi = 0; pi < 4; pi++) {
            float v = av[pi];
#pragma unroll
            for (int o = 16; o; o >>= 1) v += __shfl_xor_sync(0xffffffffu, v, o);
            if (lane == 0) agg_sh[w * 4 + pi] = v;
        }
        __syncthreads();

        // ---- GRU combiner (row (b,i)), h0 = 0 ----
        if (tid < 3 * Dc) {
            const float* wrow = w_ih + tid * Dc;
            float g = b_ih[tid];
#pragma unroll
            for (int d = 0; d < Dc; d++) g = fmaf(x1_sh[d], wrow[d], g);
            gi_sh[tid] = g;
        }
        __syncthreads();
        if (tid < Dc) {
            const float r = sigmoidf_(gi_sh[tid] + b_hh[tid]);
            const float z = sigmoidf_(gi_sh[Dc + tid] + b_hh[Dc + tid]);
            const float n = tanhf(gi_sh[2 * Dc + tid] + r * b_hh[2 * Dc + tid]);
            h1_sh[tid] = (1.0f - z) * n;   // + z*h0, h0 = 0
        }
        __syncthreads();
        if (tid < 3 * Dc) {
            const float* wi = w_ih + tid * Dc;
            const float* wh = w_hh + tid * Dc;
            float g  = b_ih[tid];
            float gh = b_hh[tid];
#pragma unroll
            for (int d = 0; d < Dc; d++) {
                g  = fmaf(agg_sh[d], wi[d], g);
                gh = fmaf(h1_sh[d], wh[d], gh);
            }
            gi_sh[tid] = g;
            gh_sh[tid] = gh;
        }
        __syncthreads();
        if (tid < Dc) {
            const float r = sigmoidf_(gi_sh[tid] + gh_sh[tid]);
            const float z = sigmoidf_(gi_sh[Dc + tid] + gh_sh[Dc + tid]);
            const float n = tanhf(gi_sh[2 * Dc + tid] + r * gh_sh[2 * Dc + tid]);
            out[((size_t)b * Nc + i) * Dc + tid] = (1.0f - z) * n + z * h1_sh[tid];
        }
    }
}

} // namespace

extern "C" void kernel_launch(void* const* d_in, const int* in_sizes, int n_in,
                              void* d_out, int out_size) {
    const float* nodes = (const float*)d_in[0];
    const float* edges = (const float*)d_in[1];
    const float* mask  = (const float*)d_in[2];
    const float* W_agg = (const float*)d_in[3];
    const float* b_agg = (const float*)d_in[4];
    const float* w_ih  = (const float*)d_in[5];
    const float* w_hh  = (const float*)d_in[6];
    const float* b_ih  = (const float*)d_in[7];
    const float* b_hh  = (const float*)d_in[8];
    float* out = (float*)d_out;

    cudaFuncSetAttribute(mp_layer_kernel,
                         cudaFuncAttributeMaxDynamicSharedMemorySize, SMEM_BYTES);
    mp_layer_kernel<<<GRID, THREADS, SMEM_BYTES>>>(nodes, edges, mask, W_agg, b_agg,
                                                   w_ih, w_hh, b_ih, b_hh, out);
}

// round 7
// speedup vs baseline: 2.6040x; 1.6648x over previous
#include <cuda_runtime.h>
#include <math.h>
#include <stdint.h>

namespace {

constexpr int Bc = 32, Nc = 96, Dc = 32, Fc = 16;
constexpr int THREADS = 512;        // 16 warps; warp w owns output cols [w*64, w*64+64)
constexpr int GRID    = 152;        // persistent: 1 CTA per SM
constexpr int NTILES  = Bc * Nc;    // 3072 (b,i) tiles
constexpr int EPAD    = 20;

// SMEM byte offsets
constexpr int OFF_WFRAG = 0;                 // 128 nt x 2 ks x 32 lane float2 = 65536
constexpr int OFF_BIAS  = 65536;             // 1024 f = 4096
constexpr int OFF_E     = 69632;             // 96 x 20 u32 = 7680
constexpr int OFF_MN    = 77312;             // 1536 float2 = 12288
constexpr int OFF_WIH   = 89600;             // w_ih^T  [32][96] = 12288
constexpr int OFF_WHH   = 101888;            // w_hh^T  [32][96] = 12288
constexpr int OFF_ACT   = 114176;            // 96 int
constexpr int OFF_CNT   = 114560;            // int
constexpr int OFF_AGG   = 114576;            // 32 f
constexpr int OFF_X1    = 114704;            // 32 f
constexpr int OFF_H1    = 114832;            // 32 f
constexpr int OFF_GI    = 114960;            // 96 f
constexpr int OFF_GH    = 115344;            // 96 f
constexpr int SMEM_BYTES = 115728;

__device__ __forceinline__ float sigmoidf_(float x) { return 1.0f / (1.0f + expf(-x)); }

__device__ __forceinline__ uint32_t f2tf32(float x) {
    uint32_t r;
    asm("cvt.rna.tf32.f32 %0, %1;" : "=r"(r) : "f"(x));
    return r;
}

__device__ __forceinline__ void mma_tf32(float& d0, float& d1, float& d2, float& d3,
                                         uint32_t a0, uint32_t a1, uint32_t a2, uint32_t a3,
                                         uint32_t b0, uint32_t b1) {
    asm volatile(
        "mma.sync.aligned.m16n8k8.row.col.f32.tf32.tf32.f32 "
        "{%0,%1,%2,%3}, {%4,%5,%6,%7}, {%8,%9}, {%0,%1,%2,%3};"
        : "+f"(d0), "+f"(d1), "+f"(d2), "+f"(d3)
        : "r"(a0), "r"(a1), "r"(a2), "r"(a3), "r"(b0), "r"(b1));
}

// mn storage: (e,qp) -> float2 slot, bijective per 32-slot block, conflict-free
// LDS.64 in the epilogue (one lane per 8B bank).
__device__ __forceinline__ int mn_idx(int e, int qp) {
    return (((qp >> 2) * 12 + (e >> 3)) << 5) + ((qp & 3) << 3) + (e & 7);
}

__global__ __launch_bounds__(THREADS, 1)
void mp_layer_kernel(const float* __restrict__ nodes,   // [B, N, D]
                     const float* __restrict__ edges,   // [B, N*N, F]
                     const float* __restrict__ mask,    // [B, N*N, 1] (0/1)
                     const float* __restrict__ W_agg,   // [F, D*D]
                     const float* __restrict__ b_agg,   // [D*D]
                     const float* __restrict__ w_ih,    // [3D, D]
                     const float* __restrict__ w_hh,    // [3D, D]
                     const float* __restrict__ b_ih,    // [3D]
                     const float* __restrict__ b_hh,    // [3D]
                     float* __restrict__ out)           // [B, N, D]
{
    extern __shared__ char smem[];
    float2*   wfrag    = reinterpret_cast<float2*>(smem + OFF_WFRAG);
    float*    bias_sh  = reinterpret_cast<float*>(smem + OFF_BIAS);
    uint32_t* E_sh     = reinterpret_cast<uint32_t*>(smem + OFF_E);
    float2*   mnS      = reinterpret_cast<float2*>(smem + OFF_MN);
    float*    wihT     = reinterpret_cast<float*>(smem + OFF_WIH);
    float*    whhT     = reinterpret_cast<float*>(smem + OFF_WHH);
    int*      active_sh= reinterpret_cast<int*>(smem + OFF_ACT);
    int*      count_sh = reinterpret_cast<int*>(smem + OFF_CNT);
    float*    agg_sh   = reinterpret_cast<float*>(smem + OFF_AGG);
    float*    x1_sh    = reinterpret_cast<float*>(smem + OFF_X1);
    float*    h1_sh    = reinterpret_cast<float*>(smem + OFF_H1);
    float*    gi_sh    = reinterpret_cast<float*>(smem + OFF_GI);
    float*    gh_sh    = reinterpret_cast<float*>(smem + OFF_GH);

    const int tid  = threadIdx.x;
    const int lane = tid & 31;
    const int w    = tid >> 5;

    // ---- One-time per CTA: W fragments (tf32), bias, transposed GRU weights ----
    for (int idx = tid; idx < 128 * 2 * 32; idx += THREADS) {
        const int l  = idx & 31;
        const int ks = (idx >> 5) & 1;
        const int nt = idx >> 6;
        const int col = nt * 8 + (l >> 2);
        const int k0  = ks * 8 + (l & 3);
        float2 v;
        v.x = __uint_as_float(f2tf32(W_agg[k0 * 1024 + col]));
        v.y = __uint_as_float(f2tf32(W_agg[(k0 + 4) * 1024 + col]));
        wfrag[idx] = v;
    }
    for (int c = tid; c < 1024; c += THREADS) bias_sh[c] = b_agg[c];
    for (int idx = tid; idx < 96 * 32; idx += THREADS) {
        const int g = idx >> 5;
        const int d = idx & 31;
        wihT[d * 96 + g] = w_ih[idx];   // coalesced load, strided store (once)
        whhT[d * 96 + g] = w_hh[idx];
    }

    // ---- Persistent tile loop ----
    for (int tile = blockIdx.x; tile < NTILES; tile += GRID) {
        const int b = tile / Nc;
        const int i = tile - b * Nc;
        const size_t ebase = ((size_t)b * (Nc * Nc) + (size_t)i * Nc) * Fc;
        const size_t mbase = (size_t)b * (Nc * Nc) + (size_t)i * Nc;
        const size_t nbase = (size_t)b * (Nc * Dc);

        __syncthreads();   // previous tile fully consumed

        // Warp 0: compact active edges. Warp 1: stage x1.
        if (tid < 32) {
            int cnt = 0;
#pragma unroll
            for (int rr = 0; rr < Nc / 32; rr++) {
                const int j = rr * 32 + lane;
                const bool act = (mask[mbase + j] != 0.0f);
                const unsigned bal = __ballot_sync(0xffffffffu, act);
                if (act) active_sh[cnt + __popc(bal & ((1u << lane) - 1u))] = j;
                cnt += __popc(bal);
            }
            if (lane == 0) count_sh[0] = cnt;
        } else if (tid >= 32 && tid < 64) {
            x1_sh[lane] = nodes[nbase + (size_t)i * Dc + lane];
        }
        __syncthreads();

        const int cnt    = count_sh[0];
        const int mtiles = (cnt + 15) >> 4;
        const int padcnt = mtiles << 4;

        // Stage E_act (tf32, zero-padded rows) and mn (zero-padded).
        for (int idx = tid; idx < padcnt * Fc; idx += THREADS) {
            const int a = idx >> 4;
            const int f = idx & 15;
            uint32_t v = 0u;
            if (a < cnt) v = f2tf32(edges[ebase + (size_t)active_sh[a] * Fc + f]);
            E_sh[a * EPAD + f] = v;
        }
        for (int idx = tid; idx < padcnt * 16; idx += THREADS) {
            const int a  = idx >> 4;
            const int qp = idx & 15;
            float2 v = make_float2(0.0f, 0.0f);
            if (a < cnt) {
                const float* src = nodes + nbase + (size_t)active_sh[a] * Dc + qp * 2;
                v = *reinterpret_cast<const float2*>(src);
            }
            mnS[mn_idx(a, qp)] = v;
        }
        __syncthreads();

        // ---- MMA + fused epilogue. Warp w owns n-tiles w*8 .. w*8+7. ----
        float acc0 = 0.0f, acc1 = 0.0f;
        const int l4  = lane & 3;
        const int lr  = lane >> 2;

        for (int mt = 0; mt < mtiles; mt++) {
            const int r0 = mt * 16 + lr;
            const uint32_t* e0p = E_sh + r0 * EPAD;
            const uint32_t* e1p = E_sh + (r0 + 8) * EPAD;
            const uint32_t a00 = e0p[l4],      a01 = e1p[l4];
            const uint32_t a02 = e0p[l4 + 4],  a03 = e1p[l4 + 4];
            const uint32_t a10 = e0p[l4 + 8],  a11 = e1p[l4 + 8];
            const uint32_t a12 = e0p[l4 + 12], a13 = e1p[l4 + 12];

#pragma unroll
            for (int t = 0; t < 8; t++) {
                const int ntb = (w * 8 + t) * 2;
                const float2 bf0 = wfrag[(ntb)     * 32 + lane];
                const float2 bf1 = wfrag[(ntb + 1) * 32 + lane];

                float d0 = 0.0f, d1 = 0.0f, d2 = 0.0f, d3 = 0.0f;
                mma_tf32(d0, d1, d2, d3, a00, a01, a02, a03,
                         __float_as_uint(bf0.x), __float_as_uint(bf0.y));
                mma_tf32(d0, d1, d2, d3, a10, a11, a12, a13,
                         __float_as_uint(bf1.x), __float_as_uint(bf1.y));

                const float2 bb = *reinterpret_cast<const float2*>(
                    bias_sh + w * 64 + t * 8 + l4 * 2);
                d0 = fmaxf(d0 + bb.x, 0.0f);
                d1 = fmaxf(d1 + bb.y, 0.0f);
                d2 = fmaxf(d2 + bb.x, 0.0f);
                d3 = fmaxf(d3 + bb.y, 0.0f);

                const int qp = (t & 3) * 4 + l4;
                const float2 m0 = mnS[mn_idx(r0, qp)];
                const float2 m1 = mnS[mn_idx(r0 + 8, qp)];
                const float c = fmaf(d0, m0.x, fmaf(d1, m0.y,
                                fmaf(d2, m1.x, d3 * m1.y)));
                if ((t >> 2) == 0) acc0 += c;
                else acc1 += c;
            }
        }

        // Warp-reduce the 2 p-accumulators -> agg_sh[w*2 + pi]
        {
            float v0 = acc0, v1 = acc1;
#pragma unroll
            for (int o = 16; o; o >>= 1) {
                v0 += __shfl_xor_sync(0xffffffffu, v0, o);
                v1 += __shfl_xor_sync(0xffffffffu, v1, o);
            }
            if (lane == 0) { agg_sh[w * 2] = v0; agg_sh[w * 2 + 1] = v1; }
        }
        __syncthreads();

        // ---- GRU combiner (row (b,i)), h0 = 0; weights from SMEM, coalesced ----
        if (tid < 3 * Dc) {
            float g = b_ih[tid];
#pragma unroll
            for (int d = 0; d < Dc; d++) g = fmaf(x1_sh[d], wihT[d * 96 + tid], g);
            gi_sh[tid] = g;
        }
        __syncthreads();
        if (tid < Dc) {
            const float r = sigmoidf_(gi_sh[tid] + b_hh[tid]);
            const float z = sigmoidf_(gi_sh[Dc + tid] + b_hh[Dc + tid]);
            const float n = tanhf(gi_sh[2 * Dc + tid] + r * b_hh[2 * Dc + tid]);
            h1_sh[tid] = (1.0f - z) * n;   // + z*h0, h0 = 0
        }
        __syncthreads();
        if (tid < 3 * Dc) {
            float g  = b_ih[tid];
            float gh = b_hh[tid];
#pragma unroll
            for (int d = 0; d < Dc; d++) {
                g  = fmaf(agg_sh[d], wihT[d * 96 + tid], g);
                gh = fmaf(h1_sh[d],  whhT[d * 96 + tid], gh);
            }
            gi_sh[tid] = g;
            gh_sh[tid] = gh;
        }
        __syncthreads();
        if (tid < Dc) {
            const float r = sigmoidf_(gi_sh[tid] + gh_sh[tid]);
            const float z = sigmoidf_(gi_sh[Dc + tid] + gh_sh[Dc + tid]);
            const float n = tanhf(gi_sh[2 * Dc + tid] + r * gh_sh[2 * Dc + tid]);
            out[((size_t)b * Nc + i) * Dc + tid] = (1.0f - z) * n + z * h1_sh[tid];
        }
    }
}

} // namespace

extern "C" void kernel_launch(void* const* d_in, const int* in_sizes, int n_in,
                              void* d_out, int out_size) {
    const float* nodes = (const float*)d_in[0];
    const float* edges = (const float*)d_in[1];
    const float* mask  = (const float*)d_in[2];
    const float* W_agg = (const float*)d_in[3];
    const float* b_agg = (const float*)d_in[4];
    const float* w_ih  = (const float*)d_in[5];
    const float* w_hh  = (const float*)d_in[6];
    const float* b_ih  = (const float*)d_in[7];
    const float* b_hh  = (const float*)d_in[8];
    float* out = (float*)d_out;

    cudaFuncSetAttribute(mp_layer_kernel,
                         cudaFuncAttributeMaxDynamicSharedMemorySize, SMEM_BYTES);
    mp_layer_kernel<<<GRID, THREADS, SMEM_BYTES>>>(nodes, edges, mask, W_agg, b_agg,
                                                   w_ih, w_hh, b_ih, b_hh, out);
}

// round 8
// speedup vs baseline: 3.4659x; 1.3310x over previous
#include <cuda_runtime.h>
#include <math.h>
#include <stdint.h>

namespace {

constexpr int Bc = 32, Nc = 96, Dc = 32, Fc = 16;
constexpr int THREADS = 512;        // two independent 256-thread halves
constexpr int HALF    = 256;
constexpr int GRID    = 152;        // persistent: 1 CTA per SM, 2 tile-streams per CTA
constexpr int NTILES  = Bc * Nc;    // 3072
constexpr int EPAD    = 20;

// Shared (read-only after init)
constexpr int OFF_WFRAG = 0;                 // 128 nt x 2 ks x 32 lane float2 = 65536
constexpr int OFF_BIAS  = 65536;             // 1024 f = 4096
constexpr int OFF_WIH   = 69632;             // w_ih^T [32][96] = 12288
constexpr int OFF_WHH   = 81920;             // w_hh^T [32][96] = 12288
// Per-half block (h = 0,1), 21760 bytes each
constexpr int OFF_HALF0 = 94208;
constexpr int HALF_BYTES = 21760;
constexpr int HO_E   = 0;       // 96 x 20 u32 = 7680
constexpr int HO_MN  = 7680;    // 1536 float2 = 12288
constexpr int HO_ACT = 19968;   // 96 int = 384
constexpr int HO_CNT = 20352;   // int
constexpr int HO_AGG = 20368;   // 32 f
constexpr int HO_X1  = 20496;   // 32 f
constexpr int HO_H1  = 20624;   // 32 f
constexpr int HO_GI  = 20752;   // 96 f
constexpr int HO_GH  = 21136;   // 96 f
constexpr int SMEM_BYTES = OFF_HALF0 + 2 * HALF_BYTES;   // 137728

__device__ __forceinline__ float sigmoidf_(float x) { return 1.0f / (1.0f + expf(-x)); }

__device__ __forceinline__ uint32_t f2tf32(float x) {
    uint32_t r;
    asm("cvt.rna.tf32.f32 %0, %1;" : "=r"(r) : "f"(x));
    return r;
}

__device__ __forceinline__ void mma_tf32(float& d0, float& d1, float& d2, float& d3,
                                         uint32_t a0, uint32_t a1, uint32_t a2, uint32_t a3,
                                         uint32_t b0, uint32_t b1) {
    asm volatile(
        "mma.sync.aligned.m16n8k8.row.col.f32.tf32.tf32.f32 "
        "{%0,%1,%2,%3}, {%4,%5,%6,%7}, {%8,%9}, {%0,%1,%2,%3};"
        : "+f"(d0), "+f"(d1), "+f"(d2), "+f"(d3)
        : "r"(a0), "r"(a1), "r"(a2), "r"(a3), "r"(b0), "r"(b1));
}

// mn storage: (e,qp) -> float2 slot, bijective per 32-slot block, conflict-free
// LDS.64 in the epilogue.
__device__ __forceinline__ int mn_idx(int e, int qp) {
    return (((qp >> 2) * 12 + (e >> 3)) << 5) + ((qp & 3) << 3) + (e & 7);
}

__device__ __forceinline__ void half_bar(int h) {
    asm volatile("bar.sync %0, %1;" :: "r"(h + 1), "r"(HALF) : "memory");
}

__global__ __launch_bounds__(THREADS, 1)
void mp_layer_kernel(const float* __restrict__ nodes,   // [B, N, D]
                     const float* __restrict__ edges,   // [B, N*N, F]
                     const float* __restrict__ mask,    // [B, N*N, 1] (0/1)
                     const float* __restrict__ W_agg,   // [F, D*D]
                     const float* __restrict__ b_agg,   // [D*D]
                     const float* __restrict__ w_ih,    // [3D, D]
                     const float* __restrict__ w_hh,    // [3D, D]
                     const float* __restrict__ b_ih,    // [3D]
                     const float* __restrict__ b_hh,    // [3D]
                     float* __restrict__ out)           // [B, N, D]
{
    extern __shared__ char smem[];
    float2* wfrag   = reinterpret_cast<float2*>(smem + OFF_WFRAG);
    float*  bias_sh = reinterpret_cast<float*>(smem + OFF_BIAS);
    float*  wihT    = reinterpret_cast<float*>(smem + OFF_WIH);
    float*  whhT    = reinterpret_cast<float*>(smem + OFF_WHH);

    const int tid  = threadIdx.x;

    // ---- One-time per CTA: W fragments (tf32), bias, transposed GRU weights ----
    for (int idx = tid; idx < 128 * 2 * 32; idx += THREADS) {
        const int l  = idx & 31;
        const int ks = (idx >> 5) & 1;
        const int nt = idx >> 6;
        const int col = nt * 8 + (l >> 2);
        const int k0  = ks * 8 + (l & 3);
        float2 v;
        v.x = __uint_as_float(f2tf32(W_agg[k0 * 1024 + col]));
        v.y = __uint_as_float(f2tf32(W_agg[(k0 + 4) * 1024 + col]));
        wfrag[idx] = v;
    }
    for (int c = tid; c < 1024; c += THREADS) bias_sh[c] = b_agg[c];
    for (int idx = tid; idx < 96 * 32; idx += THREADS) {
        const int g = idx >> 5;
        const int d = idx & 31;
        wihT[d * 96 + g] = w_ih[idx];
        whhT[d * 96 + g] = w_hh[idx];
    }
    __syncthreads();

    // ---- Half-local views ----
    const int h    = tid >> 8;          // 0 or 1
    const int tidh = tid & (HALF - 1);
    const int lane = tid & 31;
    const int wh   = (tid >> 5) & 7;    // warp id within half

    char* hbase = smem + OFF_HALF0 + h * HALF_BYTES;
    uint32_t* E_sh      = reinterpret_cast<uint32_t*>(hbase + HO_E);
    float2*   mnS       = reinterpret_cast<float2*>(hbase + HO_MN);
    int*      active_sh = reinterpret_cast<int*>(hbase + HO_ACT);
    int*      count_sh  = reinterpret_cast<int*>(hbase + HO_CNT);
    float*    agg_sh    = reinterpret_cast<float*>(hbase + HO_AGG);
    float*    x1_sh     = reinterpret_cast<float*>(hbase + HO_X1);
    float*    h1_sh     = reinterpret_cast<float*>(hbase + HO_H1);
    float*    gi_sh     = reinterpret_cast<float*>(hbase + HO_GI);
    float*    gh_sh     = reinterpret_cast<float*>(hbase + HO_GH);

    // ---- Per-half persistent tile loop ----
    for (int tile = blockIdx.x * 2 + h; tile < NTILES; tile += GRID * 2) {
        const int b = tile / Nc;
        const int i = tile - b * Nc;
        const size_t ebase = ((size_t)b * (Nc * Nc) + (size_t)i * Nc) * Fc;
        const size_t mbase = (size_t)b * (Nc * Nc) + (size_t)i * Nc;
        const size_t nbase = (size_t)b * (Nc * Dc);

        // Warp 0 of half: compact active edges. Warp 1: stage x1.
        if (tidh < 32) {
            int cnt = 0;
#pragma unroll
            for (int rr = 0; rr < Nc / 32; rr++) {
                const int j = rr * 32 + lane;
                const bool act = (mask[mbase + j] != 0.0f);
                const unsigned bal = __ballot_sync(0xffffffffu, act);
                if (act) active_sh[cnt + __popc(bal & ((1u << lane) - 1u))] = j;
                cnt += __popc(bal);
            }
            if (lane == 0) count_sh[0] = cnt;
        } else if (tidh >= 32 && tidh < 64) {
            x1_sh[lane] = nodes[nbase + (size_t)i * Dc + lane];
        }
        half_bar(h);

        const int cnt    = count_sh[0];
        const int mtiles = (cnt + 15) >> 4;
        const int padcnt = mtiles << 4;

        // Stage E_act (tf32, zero-padded rows) and mn (zero-padded).
        for (int idx = tidh; idx < padcnt * Fc; idx += HALF) {
            const int a = idx >> 4;
            const int f = idx & 15;
            uint32_t v = 0u;
            if (a < cnt) v = f2tf32(edges[ebase + (size_t)active_sh[a] * Fc + f]);
            E_sh[a * EPAD + f] = v;
        }
        for (int idx = tidh; idx < padcnt * 16; idx += HALF) {
            const int a  = idx >> 4;
            const int qp = idx & 15;
            float2 v = make_float2(0.0f, 0.0f);
            if (a < cnt) {
                const float* src = nodes + nbase + (size_t)active_sh[a] * Dc + qp * 2;
                v = *reinterpret_cast<const float2*>(src);
            }
            mnS[mn_idx(a, qp)] = v;
        }
        half_bar(h);

        // ---- MMA + fused epilogue. Warp wh owns n-tiles wh*16 .. wh*16+15. ----
        float acc0 = 0.0f, acc1 = 0.0f, acc2 = 0.0f, acc3 = 0.0f;
        const int l4 = lane & 3;
        const int lr = lane >> 2;

        for (int mt = 0; mt < mtiles; mt++) {
            const int r0 = mt * 16 + lr;
            const uint32_t* e0p = E_sh + r0 * EPAD;
            const uint32_t* e1p = E_sh + (r0 + 8) * EPAD;
            const uint32_t a00 = e0p[l4],      a01 = e1p[l4];
            const uint32_t a02 = e0p[l4 + 4],  a03 = e1p[l4 + 4];
            const uint32_t a10 = e0p[l4 + 8],  a11 = e1p[l4 + 8];
            const uint32_t a12 = e0p[l4 + 12], a13 = e1p[l4 + 12];

#pragma unroll
            for (int t = 0; t < 16; t++) {
                const int ntb = (wh * 16 + t) * 2;
                const float2 bf0 = wfrag[(ntb)     * 32 + lane];
                const float2 bf1 = wfrag[(ntb + 1) * 32 + lane];

                float d0 = 0.0f, d1 = 0.0f, d2 = 0.0f, d3 = 0.0f;
                mma_tf32(d0, d1, d2, d3, a00, a01, a02, a03,
                         __float_as_uint(bf0.x), __float_as_uint(bf0.y));
                mma_tf32(d0, d1, d2, d3, a10, a11, a12, a13,
                         __float_as_uint(bf1.x), __float_as_uint(bf1.y));

                const float2 bb = *reinterpret_cast<const float2*>(
                    bias_sh + wh * 128 + t * 8 + l4 * 2);
                d0 = fmaxf(d0 + bb.x, 0.0f);
                d1 = fmaxf(d1 + bb.y, 0.0f);
                d2 = fmaxf(d2 + bb.x, 0.0f);
                d3 = fmaxf(d3 + bb.y, 0.0f);

                const int qp = (t & 3) * 4 + l4;
                const float2 m0 = mnS[mn_idx(r0, qp)];
                const float2 m1 = mnS[mn_idx(r0 + 8, qp)];
                const float c = fmaf(d0, m0.x, fmaf(d1, m0.y,
                                fmaf(d2, m1.x, d3 * m1.y)));
                if ((t >> 2) == 0) acc0 += c;
                else if ((t >> 2) == 1) acc1 += c;
                else if ((t >> 2) == 2) acc2 += c;
                else acc3 += c;
            }
        }

        // Warp-reduce the 4 p-accumulators -> agg_sh[wh*4 + pi]
        float av[4] = {acc0, acc1, acc2, acc3};
#pragma unroll
        for (int pi = 0; pi < 4; pi++) {
            float v = av[pi];
#pragma unroll
            for (int o = 16; o; o >>= 1) v += __shfl_xor_sync(0xffffffffu, v, o);
            if (lane == 0) agg_sh[wh * 4 + pi] = v;
        }
        half_bar(h);

        // ---- GRU combiner (row (b,i)), h0 = 0; weights from SMEM ----
        if (tidh < 3 * Dc) {
            float g = b_ih[tidh];
#pragma unroll
            for (int d = 0; d < Dc; d++) g = fmaf(x1_sh[d], wihT[d * 96 + tidh], g);
            gi_sh[tidh] = g;
        }
        half_bar(h);
        if (tidh < Dc) {
            const float r = sigmoidf_(gi_sh[tidh] + b_hh[tidh]);
            const float z = sigmoidf_(gi_sh[Dc + tidh] + b_hh[Dc + tidh]);
            const float n = tanhf(gi_sh[2 * Dc + tidh] + r * b_hh[2 * Dc + tidh]);
            h1_sh[tidh] = (1.0f - z) * n;   // + z*h0, h0 = 0
        }
        half_bar(h);
        if (tidh < 3 * Dc) {
            float g  = b_ih[tidh];
            float gh = b_hh[tidh];
#pragma unroll
            for (int d = 0; d < Dc; d++) {
                g  = fmaf(agg_sh[d], wihT[d * 96 + tidh], g);
                gh = fmaf(h1_sh[d],  whhT[d * 96 + tidh], gh);
            }
            gi_sh[tidh] = g;
            gh_sh[tidh] = gh;
        }
        half_bar(h);
        if (tidh < Dc) {
            const float r = sigmoidf_(gi_sh[tidh] + gh_sh[tidh]);
            const float z = sigmoidf_(gi_sh[Dc + tidh] + gh_sh[Dc + tidh]);
            const float n = tanhf(gi_sh[2 * Dc + tidh] + r * gh_sh[2 * Dc + tidh]);
            out[((size_t)b * Nc + i) * Dc + tidh] = (1.0f - z) * n + z * h1_sh[tidh];
        }
        // No loop-top barrier needed: every cross-tile SMEM hazard (x1, agg,
        // h1, active, count) is ordered by the barrier after gi2/gh2 above.
    }
}

} // namespace

extern "C" void kernel_launch(void* const* d_in, const int* in_sizes, int n_in,
                              void* d_out, int out_size) {
    const float* nodes = (const float*)d_in[0];
    const float* edges = (const float*)d_in[1];
    const float* mask  = (const float*)d_in[2];
    const float* W_agg = (const float*)d_in[3];
    const float* b_agg = (const float*)d_in[4];
    const float* w_ih  = (const float*)d_in[5];
    const float* w_hh  = (const float*)d_in[6];
    const float* b_ih  = (const float*)d_in[7];
    const float* b_hh  = (const float*)d_in[8];
    float* out = (float*)d_out;

    cudaFuncSetAttribute(mp_layer_kernel,
                         cudaFuncAttributeMaxDynamicSharedMemorySize, SMEM_BYTES);
    mp_layer_kernel<<<GRID, THREADS, SMEM_BYTES>>>(nodes, edges, mask, W_agg, b_agg,
                                                   w_ih, w_hh, b_ih, b_hh, out);
}

// round 9
// speedup vs baseline: 3.8019x; 1.0969x over previous
#include <cuda_runtime.h>
#include <math.h>
#include <stdint.h>

namespace {

constexpr int Bc = 32, Nc = 96, Dc = 32, Fc = 16;
constexpr int THREADS = 512;        // four independent 128-thread streams
constexpr int SWIDTH  = 128;
constexpr int NSTREAM = 4;
constexpr int GRID    = 152;        // persistent: 1 CTA per SM
constexpr int NTILES  = Bc * Nc;    // 3072
constexpr int EPAD    = 20;

// Shared (read-only after init)
constexpr int OFF_WFRAG = 0;                 // 128 nt x 2 ks x 32 lane float2 = 65536
constexpr int OFF_BIAS  = 65536;             // 1024 f = 4096
constexpr int OFF_WIH   = 69632;             // w_ih^T [32][96] = 12288
constexpr int OFF_WHH   = 81920;             // w_hh^T [32][96] = 12288
// Per-stream block, 21760 bytes each
constexpr int OFF_S0 = 94208;
constexpr int S_BYTES = 21760;
constexpr int SO_E   = 0;       // 96 x 20 u32 = 7680
constexpr int SO_MN  = 7680;    // 1536 float2 = 12288
constexpr int SO_ACT = 19968;   // 96 int
constexpr int SO_CNT = 20352;   // int
constexpr int SO_AGG = 20368;   // 32 f
constexpr int SO_X1  = 20496;   // 32 f
constexpr int SO_H1  = 20624;   // 32 f
constexpr int SO_GI  = 20752;   // 96 f
constexpr int SO_GH  = 21136;   // 96 f
constexpr int SMEM_BYTES = OFF_S0 + NSTREAM * S_BYTES;   // 181248

__device__ __forceinline__ float sigmoidf_(float x) { return 1.0f / (1.0f + expf(-x)); }

__device__ __forceinline__ uint32_t f2tf32(float x) {
    uint32_t r;
    asm("cvt.rna.tf32.f32 %0, %1;" : "=r"(r) : "f"(x));
    return r;
}

__device__ __forceinline__ void mma_tf32(float& d0, float& d1, float& d2, float& d3,
                                         uint32_t a0, uint32_t a1, uint32_t a2, uint32_t a3,
                                         uint32_t b0, uint32_t b1) {
    asm volatile(
        "mma.sync.aligned.m16n8k8.row.col.f32.tf32.tf32.f32 "
        "{%0,%1,%2,%3}, {%4,%5,%6,%7}, {%8,%9}, {%0,%1,%2,%3};"
        : "+f"(d0), "+f"(d1), "+f"(d2), "+f"(d3)
        : "r"(a0), "r"(a1), "r"(a2), "r"(a3), "r"(b0), "r"(b1));
}

// mn storage: (e,qp) -> float2 slot, bijective per 32-slot block, conflict-free
// LDS.64 in the epilogue.
__device__ __forceinline__ int mn_idx(int e, int qp) {
    return (((qp >> 2) * 12 + (e >> 3)) << 5) + ((qp & 3) << 3) + (e & 7);
}

__device__ __forceinline__ void stream_bar(int s) {
    asm volatile("bar.sync %0, %1;" :: "r"(s + 1), "r"(SWIDTH) : "memory");
}

__global__ __launch_bounds__(THREADS, 1)
void mp_layer_kernel(const float* __restrict__ nodes,   // [B, N, D]
                     const float* __restrict__ edges,   // [B, N*N, F]
                     const float* __restrict__ mask,    // [B, N*N, 1] (0/1)
                     const float* __restrict__ W_agg,   // [F, D*D]
                     const float* __restrict__ b_agg,   // [D*D]
                     const float* __restrict__ w_ih,    // [3D, D]
                     const float* __restrict__ w_hh,    // [3D, D]
                     const float* __restrict__ b_ih,    // [3D]
                     const float* __restrict__ b_hh,    // [3D]
                     float* __restrict__ out)           // [B, N, D]
{
    extern __shared__ char smem[];
    float2* wfrag   = reinterpret_cast<float2*>(smem + OFF_WFRAG);
    float*  bias_sh = reinterpret_cast<float*>(smem + OFF_BIAS);
    float*  wihT    = reinterpret_cast<float*>(smem + OFF_WIH);
    float*  whhT    = reinterpret_cast<float*>(smem + OFF_WHH);

    const int tid = threadIdx.x;

    // ---- One-time per CTA: W fragments (tf32), bias, transposed GRU weights ----
    for (int idx = tid; idx < 128 * 2 * 32; idx += THREADS) {
        const int l  = idx & 31;
        const int ks = (idx >> 5) & 1;
        const int nt = idx >> 6;
        const int col = nt * 8 + (l >> 2);
        const int k0  = ks * 8 + (l & 3);
        float2 v;
        v.x = __uint_as_float(f2tf32(W_agg[k0 * 1024 + col]));
        v.y = __uint_as_float(f2tf32(W_agg[(k0 + 4) * 1024 + col]));
        wfrag[idx] = v;
    }
    for (int c = tid; c < 1024; c += THREADS) bias_sh[c] = b_agg[c];
    for (int idx = tid; idx < 96 * 32; idx += THREADS) {
        const int g = idx >> 5;
        const int d = idx & 31;
        wihT[d * 96 + g] = w_ih[idx];
        whhT[d * 96 + g] = w_hh[idx];
    }
    __syncthreads();

    // ---- Stream-local views ----
    const int s    = tid >> 7;          // stream 0..3
    const int tids = tid & (SWIDTH - 1);
    const int lane = tid & 31;
    const int wq   = (tid >> 5) & 3;    // warp id within stream

    char* sbase = smem + OFF_S0 + s * S_BYTES;
    uint32_t* E_sh      = reinterpret_cast<uint32_t*>(sbase + SO_E);
    float2*   mnS       = reinterpret_cast<float2*>(sbase + SO_MN);
    int*      active_sh = reinterpret_cast<int*>(sbase + SO_ACT);
    int*      count_sh  = reinterpret_cast<int*>(sbase + SO_CNT);
    float*    agg_sh    = reinterpret_cast<float*>(sbase + SO_AGG);
    float*    x1_sh     = reinterpret_cast<float*>(sbase + SO_X1);
    float*    h1_sh     = reinterpret_cast<float*>(sbase + SO_H1);
    float*    gi_sh     = reinterpret_cast<float*>(sbase + SO_GI);
    float*    gh_sh     = reinterpret_cast<float*>(sbase + SO_GH);

    // ---- Per-stream persistent tile loop ----
    for (int tile = blockIdx.x * NSTREAM + s; tile < NTILES; tile += GRID * NSTREAM) {
        const int b = tile / Nc;
        const int i = tile - b * Nc;
        const size_t ebase = ((size_t)b * (Nc * Nc) + (size_t)i * Nc) * Fc;
        const size_t mbase = (size_t)b * (Nc * Nc) + (size_t)i * Nc;
        const size_t nbase = (size_t)b * (Nc * Dc);

        // Warp 0 of stream: compact active edges. Warp 1: stage x1.
        if (tids < 32) {
            int cnt = 0;
#pragma unroll
            for (int rr = 0; rr < Nc / 32; rr++) {
                const int j = rr * 32 + lane;
                const bool act = (mask[mbase + j] != 0.0f);
                const unsigned bal = __ballot_sync(0xffffffffu, act);
                if (act) active_sh[cnt + __popc(bal & ((1u << lane) - 1u))] = j;
                cnt += __popc(bal);
            }
            if (lane == 0) count_sh[0] = cnt;
        } else if (tids >= 32 && tids < 64) {
            x1_sh[lane] = nodes[nbase + (size_t)i * Dc + lane];
        }
        stream_bar(s);

        const int cnt    = count_sh[0];
        const int mtiles = (cnt + 15) >> 4;
        const int padcnt = mtiles << 4;

        // Stage E_act (tf32, zero-padded rows) and mn (zero-padded).
        for (int idx = tids; idx < padcnt * Fc; idx += SWIDTH) {
            const int a = idx >> 4;
            const int f = idx & 15;
            uint32_t v = 0u;
            if (a < cnt) v = f2tf32(edges[ebase + (size_t)active_sh[a] * Fc + f]);
            E_sh[a * EPAD + f] = v;
        }
        for (int idx = tids; idx < padcnt * 16; idx += SWIDTH) {
            const int a  = idx >> 4;
            const int qp = idx & 15;
            float2 v = make_float2(0.0f, 0.0f);
            if (a < cnt) {
                const float* src = nodes + nbase + (size_t)active_sh[a] * Dc + qp * 2;
                v = *reinterpret_cast<const float2*>(src);
            }
            mnS[mn_idx(a, qp)] = v;
        }
        stream_bar(s);

        // ---- MMA + fused epilogue. Warp wq owns n-tiles wq*32 .. wq*32+31. ----
        float acc[8] = {0.f, 0.f, 0.f, 0.f, 0.f, 0.f, 0.f, 0.f};
        const int l4 = lane & 3;
        const int lr = lane >> 2;

        for (int mt = 0; mt < mtiles; mt++) {
            const int r0 = mt * 16 + lr;
            const uint32_t* e0p = E_sh + r0 * EPAD;
            const uint32_t* e1p = E_sh + (r0 + 8) * EPAD;
            const uint32_t a00 = e0p[l4],      a01 = e1p[l4];
            const uint32_t a02 = e0p[l4 + 4],  a03 = e1p[l4 + 4];
            const uint32_t a10 = e0p[l4 + 8],  a11 = e1p[l4 + 8];
            const uint32_t a12 = e0p[l4 + 12], a13 = e1p[l4 + 12];

#pragma unroll
            for (int t = 0; t < 32; t++) {
                const int ntb = (wq * 32 + t) * 2;
                const float2 bf0 = wfrag[(ntb)     * 32 + lane];
                const float2 bf1 = wfrag[(ntb + 1) * 32 + lane];

                float d0 = 0.0f, d1 = 0.0f, d2 = 0.0f, d3 = 0.0f;
                mma_tf32(d0, d1, d2, d3, a00, a01, a02, a03,
                         __float_as_uint(bf0.x), __float_as_uint(bf0.y));
                mma_tf32(d0, d1, d2, d3, a10, a11, a12, a13,
                         __float_as_uint(bf1.x), __float_as_uint(bf1.y));

                const float2 bb = *reinterpret_cast<const float2*>(
                    bias_sh + wq * 256 + t * 8 + l4 * 2);
                d0 = fmaxf(d0 + bb.x, 0.0f);
                d1 = fmaxf(d1 + bb.y, 0.0f);
                d2 = fmaxf(d2 + bb.x, 0.0f);
                d3 = fmaxf(d3 + bb.y, 0.0f);

                const int qp = (t & 3) * 4 + l4;
                const float2 m0 = mnS[mn_idx(r0, qp)];
                const float2 m1 = mnS[mn_idx(r0 + 8, qp)];
                acc[t >> 2] += fmaf(d0, m0.x, fmaf(d1, m0.y,
                               fmaf(d2, m1.x, d3 * m1.y)));
            }
        }

        // Warp-reduce the 8 p-accumulators -> agg_sh[wq*8 + pi]
#pragma unroll
        for (int pi = 0; pi < 8; pi++) {
            float v = acc[pi];
#pragma unroll
            for (int o = 16; o; o >>= 1) v += __shfl_xor_sync(0xffffffffu, v, o);
            if (lane == 0) agg_sh[wq * 8 + pi] = v;
        }
        stream_bar(s);

        // ---- GRU combiner (row (b,i)), h0 = 0; weights from SMEM ----
        if (tids < 3 * Dc) {
            float g = b_ih[tids];
#pragma unroll
            for (int d = 0; d < Dc; d++) g = fmaf(x1_sh[d], wihT[d * 96 + tids], g);
            gi_sh[tids] = g;
        }
        stream_bar(s);
        if (tids < Dc) {
            const float r = sigmoidf_(gi_sh[tids] + b_hh[tids]);
            const float z = sigmoidf_(gi_sh[Dc + tids] + b_hh[Dc + tids]);
            const float n = tanhf(gi_sh[2 * Dc + tids] + r * b_hh[2 * Dc + tids]);
            h1_sh[tids] = (1.0f - z) * n;   // + z*h0, h0 = 0
        }
        stream_bar(s);
        if (tids < 3 * Dc) {
            float g  = b_ih[tids];
            float gh = b_hh[tids];
#pragma unroll
            for (int d = 0; d < Dc; d++) {
                g  = fmaf(agg_sh[d], wihT[d * 96 + tids], g);
                gh = fmaf(h1_sh[d],  whhT[d * 96 + tids], gh);
            }
            gi_sh[tids] = g;
            gh_sh[tids] = gh;
        }
        stream_bar(s);
        if (tids < Dc) {
            const float r = sigmoidf_(gi_sh[tids] + gh_sh[tids]);
            const float z = sigmoidf_(gi_sh[Dc + tids] + gh_sh[Dc + tids]);
            const float n = tanhf(gi_sh[2 * Dc + tids] + r * gh_sh[2 * Dc + tids]);
            out[((size_t)b * Nc + i) * Dc + tids] = (1.0f - z) * n + z * h1_sh[tids];
        }
        // No loop-top barrier: every cross-tile SMEM hazard is ordered by the
        // barrier after gi2/gh2 above.
    }
}

} // namespace

extern "C" void kernel_launch(void* const* d_in, const int* in_sizes, int n_in,
                              void* d_out, int out_size) {
    const float* nodes = (const float*)d_in[0];
    const float* edges = (const float*)d_in[1];
    const float* mask  = (const float*)d_in[2];
    const float* W_agg = (const float*)d_in[3];
    const float* b_agg = (const float*)d_in[4];
    const float* w_ih  = (const float*)d_in[5];
    const float* w_hh  = (const float*)d_in[6];
    const float* b_ih  = (const float*)d_in[7];
    const float* b_hh  = (const float*)d_in[8];
    float* out = (float*)d_out;

    cudaFuncSetAttribute(mp_layer_kernel,
                         cudaFuncAttributeMaxDynamicSharedMemorySize, SMEM_BYTES);
    mp_layer_kernel<<<GRID, THREADS, SMEM_BYTES>>>(nodes, edges, mask, W_agg, b_agg,
                                                   w_ih, w_hh, b_ih, b_hh, out);
}

// round 10
// speedup vs baseline: 4.2794x; 1.1256x over previous
#include <cuda_runtime.h>
#include <math.h>
#include <stdint.h>

namespace {

constexpr int Bc = 32, Nc = 96, Dc = 32, Fc = 16;
constexpr int THREADS = 512;        // four independent 128-thread streams
constexpr int SWIDTH  = 128;
constexpr int NSTREAM = 4;
constexpr int GRID    = 152;        // persistent: 1 CTA per SM
constexpr int NTILES  = Bc * Nc;    // 3072
constexpr int NSTREAMS_TOTAL = GRID * NSTREAM;   // 608
constexpr int MAXT    = 6;          // max tiles per stream (3072 = 5*608 + 32)
constexpr int EPAD    = 20;

// Shared (read-only after init)
constexpr int OFF_WFRAG = 0;                 // float4[128 nt][32 lane] = 65536
constexpr int OFF_BIAS  = 65536;             // 1024 f = 4096
constexpr int OFF_WIH   = 69632;             // w_ih^T [32][96] = 12288
constexpr int OFF_WHH   = 81920;             // w_hh^T [32][96] = 12288
// Per-stream block
constexpr int OFF_S0  = 94208;
constexpr int SO_E    = 0;       // 96 x 20 u32 = 7680
constexpr int SO_MN   = 7680;    // 1536 float2 = 12288
constexpr int SO_ACT  = 19968;   // MAXT x 96 int = 2304
constexpr int SO_X1   = 22272;   // MAXT x 32 f = 768
constexpr int SO_CNT  = 23040;   // MAXT int (padded 32)
constexpr int SO_AGG  = 23072;   // 2 x 32 f = 256 (parity double-buffer)
constexpr int SO_GI   = 23328;   // 96 f
constexpr int SO_GH   = 23712;   // 96 f
constexpr int SO_H1   = 24096;   // 32 f
constexpr int S_BYTES = 24320;
constexpr int SMEM_BYTES = OFF_S0 + NSTREAM * S_BYTES;   // 191488

__device__ __forceinline__ float sigmoidf_(float x) { return 1.0f / (1.0f + expf(-x)); }

__device__ __forceinline__ uint32_t f2tf32(float x) {
    uint32_t r;
    asm("cvt.rna.tf32.f32 %0, %1;" : "=r"(r) : "f"(x));
    return r;
}

__device__ __forceinline__ void mma_tf32(float& d0, float& d1, float& d2, float& d3,
                                         uint32_t a0, uint32_t a1, uint32_t a2, uint32_t a3,
                                         uint32_t b0, uint32_t b1) {
    asm volatile(
        "mma.sync.aligned.m16n8k8.row.col.f32.tf32.tf32.f32 "
        "{%0,%1,%2,%3}, {%4,%5,%6,%7}, {%8,%9}, {%0,%1,%2,%3};"
        : "+f"(d0), "+f"(d1), "+f"(d2), "+f"(d3)
        : "r"(a0), "r"(a1), "r"(a2), "r"(a3), "r"(b0), "r"(b1));
}

// mn storage: (e,qp) -> float2 slot, bijective per 32-slot block, conflict-free
// LDS.64 in the epilogue.
__device__ __forceinline__ int mn_idx(int e, int qp) {
    return (((qp >> 2) * 12 + (e >> 3)) << 5) + ((qp & 3) << 3) + (e & 7);
}

__device__ __forceinline__ void stream_bar(int s) {
    asm volatile("bar.sync %0, %1;" :: "r"(s + 1), "r"(SWIDTH) : "memory");
}

__global__ __launch_bounds__(THREADS, 1)
void mp_layer_kernel(const float* __restrict__ nodes,   // [B, N, D]
                     const float* __restrict__ edges,   // [B, N*N, F]
                     const float* __restrict__ mask,    // [B, N*N, 1] (0/1)
                     const float* __restrict__ W_agg,   // [F, D*D]
                     const float* __restrict__ b_agg,   // [D*D]
                     const float* __restrict__ w_ih,    // [3D, D]
                     const float* __restrict__ w_hh,    // [3D, D]
                     const float* __restrict__ b_ih,    // [3D]
                     const float* __restrict__ b_hh,    // [3D]
                     float* __restrict__ out)           // [B, N, D]
{
    extern __shared__ char smem[];
    float4* wfrag4  = reinterpret_cast<float4*>(smem + OFF_WFRAG);
    float*  bias_sh = reinterpret_cast<float*>(smem + OFF_BIAS);
    float*  wihT    = reinterpret_cast<float*>(smem + OFF_WIH);
    float*  whhT    = reinterpret_cast<float*>(smem + OFF_WHH);

    const int tid = threadIdx.x;

    // ---- One-time per CTA: W fragments (tf32, both k-steps packed), bias,
    //      transposed GRU weights ----
    for (int idx = tid; idx < 128 * 32; idx += THREADS) {
        const int l  = idx & 31;
        const int nt = idx >> 5;
        const int col = nt * 8 + (l >> 2);
        const int k   = l & 3;
        float4 v;
        v.x = __uint_as_float(f2tf32(W_agg[(k)      * 1024 + col]));
        v.y = __uint_as_float(f2tf32(W_agg[(k + 4)  * 1024 + col]));
        v.z = __uint_as_float(f2tf32(W_agg[(k + 8)  * 1024 + col]));
        v.w = __uint_as_float(f2tf32(W_agg[(k + 12) * 1024 + col]));
        wfrag4[idx] = v;
    }
    for (int c = tid; c < 1024; c += THREADS) bias_sh[c] = b_agg[c];
    for (int idx = tid; idx < 96 * 32; idx += THREADS) {
        const int g = idx >> 5;
        const int d = idx & 31;
        wihT[d * 96 + g] = w_ih[idx];
        whhT[d * 96 + g] = w_hh[idx];
    }
    __syncthreads();

    // ---- Stream-local views ----
    const int s    = tid >> 7;          // stream 0..3
    const int tids = tid & (SWIDTH - 1);
    const int lane = tid & 31;
    const int wq   = (tid >> 5) & 3;    // warp id within stream

    char* sbase = smem + OFF_S0 + s * S_BYTES;
    uint32_t* E_sh      = reinterpret_cast<uint32_t*>(sbase + SO_E);
    float2*   mnS       = reinterpret_cast<float2*>(sbase + SO_MN);
    int*      active_sh = reinterpret_cast<int*>(sbase + SO_ACT);
    int*      count_sh  = reinterpret_cast<int*>(sbase + SO_CNT);
    float*    agg_sh    = reinterpret_cast<float*>(sbase + SO_AGG);
    float*    x1_sh     = reinterpret_cast<float*>(sbase + SO_X1);
    float*    gi_sh     = reinterpret_cast<float*>(sbase + SO_GI);
    float*    gh_sh     = reinterpret_cast<float*>(sbase + SO_GH);
    float*    h1_sh     = reinterpret_cast<float*>(sbase + SO_H1);

    const int gsid = blockIdx.x * NSTREAM + s;              // global stream id
    const int ntt  = (NTILES - 1 - gsid) / NSTREAMS_TOTAL + 1;  // tiles this stream

    // ---- Prefetch phase: compact active edges + stage x1 for ALL tiles ----
    for (int tt = wq; tt < ntt; tt += 4) {
        const int tile = gsid + tt * NSTREAMS_TOTAL;
        const int b = tile / Nc;
        const int i = tile - b * Nc;
        const size_t mbase = (size_t)b * (Nc * Nc) + (size_t)i * Nc;
        int cnt = 0;
#pragma unroll
        for (int rr = 0; rr < Nc / 32; rr++) {
            const int j = rr * 32 + lane;
            const bool act = (mask[mbase + j] != 0.0f);
            const unsigned bal = __ballot_sync(0xffffffffu, act);
            if (act) active_sh[tt * 96 + cnt + __popc(bal & ((1u << lane) - 1u))] = j;
            cnt += __popc(bal);
        }
        if (lane == 0) count_sh[tt] = cnt;
        x1_sh[tt * 32 + lane] = nodes[((size_t)b * Nc + i) * Dc + lane];
    }
    stream_bar(s);

    // ---- Main pipelined tile loop ----
    for (int tt = 0; tt < ntt; tt++) {
        const int tile = gsid + tt * NSTREAMS_TOTAL;
        const int b = tile / Nc;
        const int i = tile - b * Nc;
        const size_t ebase = ((size_t)b * (Nc * Nc) + (size_t)i * Nc) * Fc;
        const size_t nbase = (size_t)b * (Nc * Dc);

        const int cnt    = count_sh[tt];
        const int mtiles = (cnt + 15) >> 4;
        const int padcnt = mtiles << 4;
        const int par    = tt & 1;

        if (wq < 3) {
            // Warps 0-2: stage E_act (tf32, zero-padded) and mn for tile tt.
            const int* act = active_sh + tt * 96;
            for (int idx = tids; idx < padcnt * Fc; idx += 96) {
                const int a = idx >> 4;
                const int f = idx & 15;
                uint32_t v = 0u;
                if (a < cnt) v = f2tf32(edges[ebase + (size_t)act[a] * Fc + f]);
                E_sh[a * EPAD + f] = v;
            }
            for (int idx = tids; idx < padcnt * 16; idx += 96) {
                const int a  = idx >> 4;
                const int qp = idx & 15;
                float2 v = make_float2(0.0f, 0.0f);
                if (a < cnt) {
                    const float* src = nodes + nbase + (size_t)act[a] * Dc + qp * 2;
                    v = *reinterpret_cast<const float2*>(src);
                }
                mnS[mn_idx(a, qp)] = v;
            }
        } else if (tt > 0) {
            // Warp 3: full GRU for tile tt-1 (in-warp, overlapped with staging).
            const int ptile = gsid + (tt - 1) * NSTREAMS_TOTAL;
            const int pb = ptile / Nc;
            const int pi = ptile - pb * Nc;
            const float* x1p  = x1_sh + (tt - 1) * 32;
            const float* aggp = agg_sh + ((tt - 1) & 1) * 32;
#pragma unroll
            for (int g3 = 0; g3 < 3; g3++) {
                const int gate = g3 * 32 + lane;
                float g = b_ih[gate];
#pragma unroll
                for (int d = 0; d < Dc; d++) g = fmaf(x1p[d], wihT[d * 96 + gate], g);
                gi_sh[gate] = g;
            }
            __syncwarp();
            {
                const float r = sigmoidf_(gi_sh[lane] + b_hh[lane]);
                const float z = sigmoidf_(gi_sh[32 + lane] + b_hh[32 + lane]);
                const float n = tanhf(gi_sh[64 + lane] + r * b_hh[64 + lane]);
                h1_sh[lane] = (1.0f - z) * n;
            }
            __syncwarp();
#pragma unroll
            for (int g3 = 0; g3 < 3; g3++) {
                const int gate = g3 * 32 + lane;
                float g  = b_ih[gate];
                float gh = b_hh[gate];
#pragma unroll
                for (int d = 0; d < Dc; d++) {
                    g  = fmaf(aggp[d],  wihT[d * 96 + gate], g);
                    gh = fmaf(h1_sh[d], whhT[d * 96 + gate], gh);
                }
                gi_sh[gate] = g;
                gh_sh[gate] = gh;
            }
            __syncwarp();
            {
                const float r = sigmoidf_(gi_sh[lane] + gh_sh[lane]);
                const float z = sigmoidf_(gi_sh[32 + lane] + gh_sh[32 + lane]);
                const float n = tanhf(gi_sh[64 + lane] + r * gh_sh[64 + lane]);
                out[((size_t)pb * Nc + pi) * Dc + lane] = (1.0f - z) * n + z * h1_sh[lane];
            }
        }
        stream_bar(s);   // staging done, GRU(tt-1) done

        // ---- MMA + fused epilogue (all 4 warps). Warp wq owns n-tiles
        //      wq*32..wq*32+31. Loop reordered c-outer so mn loads hoist. ----
        float acc[8] = {0.f, 0.f, 0.f, 0.f, 0.f, 0.f, 0.f, 0.f};
        const int l4 = lane & 3;
        const int lr = lane >> 2;

        for (int mt = 0; mt < mtiles; mt++) {
            const int r0 = mt * 16 + lr;
            const uint32_t* e0p = E_sh + r0 * EPAD;
            const uint32_t* e1p = E_sh + (r0 + 8) * EPAD;
            const uint32_t a00 = e0p[l4],      a01 = e1p[l4];
            const uint32_t a02 = e0p[l4 + 4],  a03 = e1p[l4 + 4];
            const uint32_t a10 = e0p[l4 + 8],  a11 = e1p[l4 + 8];
            const uint32_t a12 = e0p[l4 + 12], a13 = e1p[l4 + 12];

#pragma unroll
            for (int c = 0; c < 4; c++) {
                const int qp = c * 4 + l4;
                const float2 m0 = mnS[mn_idx(r0, qp)];
                const float2 m1 = mnS[mn_idx(r0 + 8, qp)];
#pragma unroll
                for (int tsub = 0; tsub < 8; tsub++) {
                    const int t  = tsub * 4 + c;
                    const int nt = wq * 32 + t;
                    const float4 bf = wfrag4[nt * 32 + lane];
                    const float2 bb = *reinterpret_cast<const float2*>(
                        bias_sh + wq * 256 + t * 8 + l4 * 2);
                    float d0 = bb.x, d1 = bb.y, d2 = bb.x, d3 = bb.y;  // bias in accum
                    mma_tf32(d0, d1, d2, d3, a00, a01, a02, a03,
                             __float_as_uint(bf.x), __float_as_uint(bf.y));
                    mma_tf32(d0, d1, d2, d3, a10, a11, a12, a13,
                             __float_as_uint(bf.z), __float_as_uint(bf.w));
                    d0 = fmaxf(d0, 0.0f);
                    d1 = fmaxf(d1, 0.0f);
                    d2 = fmaxf(d2, 0.0f);
                    d3 = fmaxf(d3, 0.0f);
                    acc[tsub] = fmaf(d0, m0.x, fmaf(d1, m0.y,
                                fmaf(d2, m1.x, fmaf(d3, m1.y, acc[tsub]))));
                }
            }
        }

        // Warp-reduce the 8 p-accumulators -> agg_sh[par][wq*8 + pi]
#pragma unroll
        for (int pi = 0; pi < 8; pi++) {
            float v = acc[pi];
#pragma unroll
            for (int o = 16; o; o >>= 1) v += __shfl_xor_sync(0xffffffffu, v, o);
            if (lane == 0) agg_sh[par * 32 + wq * 8 + pi] = v;
        }
        stream_bar(s);   // agg ready; E/mn free for next tile's staging
    }

    // ---- Drain: GRU for the last tile (warp 3) ----
    if (wq == 3 && ntt > 0) {
        const int tt = ntt - 1;
        const int ptile = gsid + tt * NSTREAMS_TOTAL;
        const int pb = ptile / Nc;
        const int pi = ptile - pb * Nc;
        const float* x1p  = x1_sh + tt * 32;
        const float* aggp = agg_sh + (tt & 1) * 32;
#pragma unroll
        for (int g3 = 0; g3 < 3; g3++) {
            const int gate = g3 * 32 + lane;
            float g = b_ih[gate];
#pragma unroll
            for (int d = 0; d < Dc; d++) g = fmaf(x1p[d], wihT[d * 96 + gate], g);
            gi_sh[gate] = g;
        }
        __syncwarp();
        {
            const float r = sigmoidf_(gi_sh[lane] + b_hh[lane]);
            const float z = sigmoidf_(gi_sh[32 + lane] + b_hh[32 + lane]);
            const float n = tanhf(gi_sh[64 + lane] + r * b_hh[64 + lane]);
            h1_sh[lane] = (1.0f - z) * n;
        }
        __syncwarp();
#pragma unroll
        for (int g3 = 0; g3 < 3; g3++) {
            const int gate = g3 * 32 + lane;
            float g  = b_ih[gate];
            float gh = b_hh[gate];
#pragma unroll
            for (int d = 0; d < Dc; d++) {
                g  = fmaf(aggp[d],  wihT[d * 96 + gate], g);
                gh = fmaf(h1_sh[d], whhT[d * 96 + gate], gh);
            }
            gi_sh[gate] = g;
            gh_sh[gate] = gh;
        }
        __syncwarp();
        {
            const float r = sigmoidf_(gi_sh[lane] + gh_sh[lane]);
            const float z = sigmoidf_(gi_sh[32 + lane] + gh_sh[32 + lane]);
            const float n = tanhf(gi_sh[64 + lane] + r * gh_sh[64 + lane]);
            out[((size_t)pb * Nc + pi) * Dc + lane] = (1.0f - z) * n + z * h1_sh[lane];
        }
    }
}

} // namespace

extern "C" void kernel_launch(void* const* d_in, const int* in_sizes, int n_in,
                              void* d_out, int out_size) {
    const float* nodes = (const float*)d_in[0];
    const float* edges = (const float*)d_in[1];
    const float* mask  = (const float*)d_in[2];
    const float* W_agg = (const float*)d_in[3];
    const float* b_agg = (const float*)d_in[4];
    const float* w_ih  = (const float*)d_in[5];
    const float* w_hh  = (const float*)d_in[6];
    const float* b_ih  = (const float*)d_in[7];
    const float* b_hh  = (const float*)d_in[8];
    float* out = (float*)d_out;

    cudaFuncSetAttribute(mp_layer_kernel,
                         cudaFuncAttributeMaxDynamicSharedMemorySize, SMEM_BYTES);
    mp_layer_kernel<<<GRID, THREADS, SMEM_BYTES>>>(nodes, edges, mask, W_agg, b_agg,
                                                   w_ih, w_hh, b_ih, b_hh, out);
}

// round 11
// speedup vs baseline: 4.4303x; 1.0353x over previous
#include <cuda_runtime.h>
#include <math.h>
#include <stdint.h>

namespace {

constexpr int Bc = 32, Nc = 96, Dc = 32, Fc = 16;
constexpr int THREADS = 512;        // four independent 128-thread streams
constexpr int SWIDTH  = 128;
constexpr int NSTREAM = 4;
constexpr int GRID    = 152;        // persistent: 1 CTA per SM
constexpr int NTILES  = Bc * Nc;    // 3072
constexpr int NSTREAMS_TOTAL = GRID * NSTREAM;   // 608
constexpr int MAXT    = 6;          // max tiles per stream
constexpr int EPAD    = 20;

// Shared (read-only after init)
constexpr int OFF_WFRAG = 0;                 // float4[128 nt][32 lane] = 65536
constexpr int OFF_BIAS  = 65536;             // 1024 f = 4096
constexpr int OFF_WIH   = 69632;             // w_ih^T [32][96] = 12288
constexpr int OFF_WHH   = 81920;             // w_hh^T [32][96] = 12288
// Per-stream block
constexpr int OFF_S0  = 94208;
constexpr int SO_E    = 0;       // 96 x 20 u32 = 7680
constexpr int SO_MN   = 7680;    // 1536 float2 = 12288
constexpr int SO_ACT  = 19968;   // MAXT x 96 int = 2304
constexpr int SO_X1   = 22272;   // MAXT x 32 f = 768
constexpr int SO_CNT  = 23040;   // MAXT int (padded 32)
constexpr int SO_AGG  = 23072;   // 2 x 32 f (parity double-buffer)
constexpr int SO_GI   = 23328;   // 96 f
constexpr int SO_GH   = 23712;   // 96 f
constexpr int SO_H1   = 24096;   // 32 f
constexpr int S_BYTES = 24320;
constexpr int SMEM_BYTES = OFF_S0 + NSTREAM * S_BYTES;   // 191488

__device__ __forceinline__ float sigmoidf_(float x) { return 1.0f / (1.0f + expf(-x)); }

__device__ __forceinline__ uint32_t f2tf32(float x) {
    uint32_t r;
    asm("cvt.rna.tf32.f32 %0, %1;" : "=r"(r) : "f"(x));
    return r;
}

__device__ __forceinline__ void mma_tf32(float& d0, float& d1, float& d2, float& d3,
                                         uint32_t a0, uint32_t a1, uint32_t a2, uint32_t a3,
                                         uint32_t b0, uint32_t b1) {
    asm volatile(
        "mma.sync.aligned.m16n8k8.row.col.f32.tf32.tf32.f32 "
        "{%0,%1,%2,%3}, {%4,%5,%6,%7}, {%8,%9}, {%0,%1,%2,%3};"
        : "+f"(d0), "+f"(d1), "+f"(d2), "+f"(d3)
        : "r"(a0), "r"(a1), "r"(a2), "r"(a3), "r"(b0), "r"(b1));
}

// mn storage: (e,qp) -> float2 slot = ((qp>>2)*12 + (e>>3))*32 + (qp&3)*8 + (e&7)
__device__ __forceinline__ int mn_idx(int e, int qp) {
    return (((qp >> 2) * 12 + (e >> 3)) << 5) + ((qp & 3) << 3) + (e & 7);
}

__device__ __forceinline__ void stream_bar(int s) {
    asm volatile("bar.sync %0, %1;" :: "r"(s + 1), "r"(SWIDTH) : "memory");
}

__global__ __launch_bounds__(THREADS, 1)
void mp_layer_kernel(const float* __restrict__ nodes,   // [B, N, D]
                     const float* __restrict__ edges,   // [B, N*N, F]
                     const float* __restrict__ mask,    // [B, N*N, 1] (0/1)
                     const float* __restrict__ W_agg,   // [F, D*D]
                     const float* __restrict__ b_agg,   // [D*D]
                     const float* __restrict__ w_ih,    // [3D, D]
                     const float* __restrict__ w_hh,    // [3D, D]
                     const float* __restrict__ b_ih,    // [3D]
                     const float* __restrict__ b_hh,    // [3D]
                     float* __restrict__ out)           // [B, N, D]
{
    extern __shared__ char smem[];
    float4* wfrag4  = reinterpret_cast<float4*>(smem + OFF_WFRAG);
    float*  bias_sh = reinterpret_cast<float*>(smem + OFF_BIAS);
    float*  wihT    = reinterpret_cast<float*>(smem + OFF_WIH);
    float*  whhT    = reinterpret_cast<float*>(smem + OFF_WHH);

    const int tid = threadIdx.x;

    // ---- One-time per CTA: W fragments (tf32, both k-steps packed), bias,
    //      transposed GRU weights ----
    for (int idx = tid; idx < 128 * 32; idx += THREADS) {
        const int l  = idx & 31;
        const int nt = idx >> 5;
        const int col = nt * 8 + (l >> 2);
        const int k   = l & 3;
        float4 v;
        v.x = __uint_as_float(f2tf32(W_agg[(k)      * 1024 + col]));
        v.y = __uint_as_float(f2tf32(W_agg[(k + 4)  * 1024 + col]));
        v.z = __uint_as_float(f2tf32(W_agg[(k + 8)  * 1024 + col]));
        v.w = __uint_as_float(f2tf32(W_agg[(k + 12) * 1024 + col]));
        wfrag4[idx] = v;
    }
    for (int c = tid; c < 1024; c += THREADS) bias_sh[c] = b_agg[c];
    for (int idx = tid; idx < 96 * 32; idx += THREADS) {
        const int g = idx >> 5;
        const int d = idx & 31;
        wihT[d * 96 + g] = w_ih[idx];
        whhT[d * 96 + g] = w_hh[idx];
    }
    __syncthreads();

    // ---- Stream-local views ----
    const int s    = tid >> 7;          // stream 0..3
    const int tids = tid & (SWIDTH - 1);
    const int lane = tid & 31;
    const int wq   = (tid >> 5) & 3;    // warp id within stream

    char* sbase = smem + OFF_S0 + s * S_BYTES;
    uint32_t* E_sh      = reinterpret_cast<uint32_t*>(sbase + SO_E);
    float2*   mnS       = reinterpret_cast<float2*>(sbase + SO_MN);
    int*      active_sh = reinterpret_cast<int*>(sbase + SO_ACT);
    int*      count_sh  = reinterpret_cast<int*>(sbase + SO_CNT);
    float*    agg_sh    = reinterpret_cast<float*>(sbase + SO_AGG);
    float*    x1_sh     = reinterpret_cast<float*>(sbase + SO_X1);
    float*    gi_sh     = reinterpret_cast<float*>(sbase + SO_GI);
    float*    gh_sh     = reinterpret_cast<float*>(sbase + SO_GH);
    float*    h1_sh     = reinterpret_cast<float*>(sbase + SO_H1);

    const int gsid = blockIdx.x * NSTREAM + s;
    const int ntt  = (NTILES - 1 - gsid) / NSTREAMS_TOTAL + 1;

    // ---- Prefetch: compact active edges + stage x1 for ALL of this stream's tiles ----
    for (int tt = wq; tt < ntt; tt += 4) {
        const int tile = gsid + tt * NSTREAMS_TOTAL;
        const int b = tile / Nc;
        const int i = tile - b * Nc;
        const size_t mbase = (size_t)b * (Nc * Nc) + (size_t)i * Nc;
        int cnt = 0;
#pragma unroll
        for (int rr = 0; rr < Nc / 32; rr++) {
            const int j = rr * 32 + lane;
            const bool act = (mask[mbase + j] != 0.0f);
            const unsigned bal = __ballot_sync(0xffffffffu, act);
            if (act) active_sh[tt * 96 + cnt + __popc(bal & ((1u << lane) - 1u))] = j;
            cnt += __popc(bal);
        }
        if (lane == 0) count_sh[tt] = cnt;
        x1_sh[tt * 32 + lane] = nodes[((size_t)b * Nc + i) * Dc + lane];
    }
    stream_bar(s);

    // Lane constants for the mainloop
    const int l4  = lane & 3;
    const int lr  = lane >> 2;
    const int mnlo = ((l4) << 3) + (lr & 7);   // within-block slot
    const int lrh  = lr >> 3;                  // 0/1: which 8-row group

    // ---- Main pipelined tile loop ----
    for (int tt = 0; tt < ntt; tt++) {
        const int tile = gsid + tt * NSTREAMS_TOTAL;
        const int b = tile / Nc;
        const int i = tile - b * Nc;
        const size_t ebase = ((size_t)b * (Nc * Nc) + (size_t)i * Nc) * Fc;
        const size_t nbase = (size_t)b * (Nc * Dc);

        const int cnt    = count_sh[tt];
        const int mtiles = (cnt + 15) >> 4;
        const int padcnt = mtiles << 4;
        const int par    = tt & 1;

        if (wq < 3) {
            // Warps 0-2: stage E_act (tf32, zero-padded) and mn for tile tt.
            const int* act = active_sh + tt * 96;
            for (int idx = tids; idx < padcnt * Fc; idx += 96) {
                const int a = idx >> 4;
                const int f = idx & 15;
                uint32_t v = 0u;
                if (a < cnt) v = f2tf32(edges[ebase + (size_t)act[a] * Fc + f]);
                E_sh[a * EPAD + f] = v;
            }
            for (int idx = tids; idx < padcnt * 16; idx += 96) {
                const int a  = idx >> 4;
                const int qp = idx & 15;
                float2 v = make_float2(0.0f, 0.0f);
                if (a < cnt) {
                    const float* src = nodes + nbase + (size_t)act[a] * Dc + qp * 2;
                    v = *reinterpret_cast<const float2*>(src);
                }
                mnS[mn_idx(a, qp)] = v;
            }
        } else if (tt > 0) {
            // Warp 3: full GRU for tile tt-1 (in-warp, overlapped with staging).
            const int ptile = gsid + (tt - 1) * NSTREAMS_TOTAL;
            const int pb = ptile / Nc;
            const int pi = ptile - pb * Nc;
            const float* x1p  = x1_sh + (tt - 1) * 32;
            const float* aggp = agg_sh + ((tt - 1) & 1) * 32;
#pragma unroll
            for (int g3 = 0; g3 < 3; g3++) {
                const int gate = g3 * 32 + lane;
                float g = b_ih[gate];
#pragma unroll
                for (int d = 0; d < Dc; d++) g = fmaf(x1p[d], wihT[d * 96 + gate], g);
                gi_sh[gate] = g;
            }
            __syncwarp();
            {
                const float r = sigmoidf_(gi_sh[lane] + b_hh[lane]);
                const float z = sigmoidf_(gi_sh[32 + lane] + b_hh[32 + lane]);
                const float n = tanhf(gi_sh[64 + lane] + r * b_hh[64 + lane]);
                h1_sh[lane] = (1.0f - z) * n;
            }
            __syncwarp();
#pragma unroll
            for (int g3 = 0; g3 < 3; g3++) {
                const int gate = g3 * 32 + lane;
                float g  = b_ih[gate];
                float gh = b_hh[gate];
#pragma unroll
                for (int d = 0; d < Dc; d++) {
                    g  = fmaf(aggp[d],  wihT[d * 96 + gate], g);
                    gh = fmaf(h1_sh[d], whhT[d * 96 + gate], gh);
                }
                gi_sh[gate] = g;
                gh_sh[gate] = gh;
            }
            __syncwarp();
            {
                const float r = sigmoidf_(gi_sh[lane] + gh_sh[lane]);
                const float z = sigmoidf_(gi_sh[32 + lane] + gh_sh[32 + lane]);
                const float n = tanhf(gi_sh[64 + lane] + r * gh_sh[64 + lane]);
                out[((size_t)pb * Nc + pi) * Dc + lane] = (1.0f - z) * n + z * h1_sh[lane];
            }
        }
        stream_bar(s);   // staging done, GRU(tt-1) done

        // ---- MMA + fused epilogue. Warp wq owns n-tiles wq*32..wq*32+31.
        //      m-blocks processed in PAIRS: wfrag/bias loaded once per
        //      (c,tsub), shared by 4 MMAs. ----
        float acc[8] = {0.f, 0.f, 0.f, 0.f, 0.f, 0.f, 0.f, 0.f};

        int mt = 0;
        for (; mt + 2 <= mtiles; mt += 2) {
            const int r0 = mt * 16 + lr;
            const uint32_t* e0p = E_sh + r0 * EPAD;
            const uint32_t a00 = e0p[l4],            a01 = e0p[8*EPAD + l4];
            const uint32_t a02 = e0p[l4 + 4],        a03 = e0p[8*EPAD + l4 + 4];
            const uint32_t a10 = e0p[l4 + 8],        a11 = e0p[8*EPAD + l4 + 8];
            const uint32_t a12 = e0p[l4 + 12],       a13 = e0p[8*EPAD + l4 + 12];
            const uint32_t b00 = e0p[16*EPAD + l4],      b01 = e0p[24*EPAD + l4];
            const uint32_t b02 = e0p[16*EPAD + l4 + 4],  b03 = e0p[24*EPAD + l4 + 4];
            const uint32_t b10 = e0p[16*EPAD + l4 + 8],  b11 = e0p[24*EPAD + l4 + 8];
            const uint32_t b12 = e0p[16*EPAD + l4 + 12], b13 = e0p[24*EPAD + l4 + 12];
            const int blk0 = mt * 2 + lrh;   // e>>3 for row r0

#pragma unroll
            for (int c = 0; c < 4; c++) {
                const float2* mp = mnS + ((c * 12 + blk0) << 5) + mnlo;
                const float2 m0 = mp[0];          // rows mt*16 + lr
                const float2 m1 = mp[32];         // +8
                const float2 m2 = mp[64];         // +16
                const float2 m3 = mp[96];         // +24
                const float4* wp = wfrag4 + (wq * 32 + c) * 32 + lane;
                const float2* bp = reinterpret_cast<const float2*>(
                    bias_sh + wq * 256 + c * 8 + l4 * 2);
#pragma unroll
                for (int tsub = 0; tsub < 8; tsub++) {
                    const float4 bf = *wp;  wp += 128;
                    const float2 bb = *bp;  bp += 16;
                    float d0 = bb.x, d1 = bb.y, d2 = bb.x, d3 = bb.y;
                    float f0 = bb.x, f1 = bb.y, f2 = bb.x, f3 = bb.y;
                    mma_tf32(d0, d1, d2, d3, a00, a01, a02, a03,
                             __float_as_uint(bf.x), __float_as_uint(bf.y));
                    mma_tf32(d0, d1, d2, d3, a10, a11, a12, a13,
                             __float_as_uint(bf.z), __float_as_uint(bf.w));
                    mma_tf32(f0, f1, f2, f3, b00, b01, b02, b03,
                             __float_as_uint(bf.x), __float_as_uint(bf.y));
                    mma_tf32(f0, f1, f2, f3, b10, b11, b12, b13,
                             __float_as_uint(bf.z), __float_as_uint(bf.w));
                    d0 = fmaxf(d0, 0.0f); d1 = fmaxf(d1, 0.0f);
                    d2 = fmaxf(d2, 0.0f); d3 = fmaxf(d3, 0.0f);
                    f0 = fmaxf(f0, 0.0f); f1 = fmaxf(f1, 0.0f);
                    f2 = fmaxf(f2, 0.0f); f3 = fmaxf(f3, 0.0f);
                    float v = fmaf(d0, m0.x, fmaf(d1, m0.y,
                              fmaf(d2, m1.x, fmaf(d3, m1.y, acc[tsub]))));
                    acc[tsub] = fmaf(f0, m2.x, fmaf(f1, m2.y,
                                fmaf(f2, m3.x, fmaf(f3, m3.y, v))));
                }
            }
        }
        if (mt < mtiles) {   // single-block tail (odd mtiles)
            const int r0 = mt * 16 + lr;
            const uint32_t* e0p = E_sh + r0 * EPAD;
            const uint32_t a00 = e0p[l4],      a01 = e0p[8*EPAD + l4];
            const uint32_t a02 = e0p[l4 + 4],  a03 = e0p[8*EPAD + l4 + 4];
            const uint32_t a10 = e0p[l4 + 8],  a11 = e0p[8*EPAD + l4 + 8];
            const uint32_t a12 = e0p[l4 + 12], a13 = e0p[8*EPAD + l4 + 12];
            const int blk0 = mt * 2 + lrh;
#pragma unroll
            for (int c = 0; c < 4; c++) {
                const float2* mp = mnS + ((c * 12 + blk0) << 5) + mnlo;
                const float2 m0 = mp[0];
                const float2 m1 = mp[32];
                const float4* wp = wfrag4 + (wq * 32 + c) * 32 + lane;
                const float2* bp = reinterpret_cast<const float2*>(
                    bias_sh + wq * 256 + c * 8 + l4 * 2);
#pragma unroll
                for (int tsub = 0; tsub < 8; tsub++) {
                    const float4 bf = *wp;  wp += 128;
                    const float2 bb = *bp;  bp += 16;
                    float d0 = bb.x, d1 = bb.y, d2 = bb.x, d3 = bb.y;
                    mma_tf32(d0, d1, d2, d3, a00, a01, a02, a03,
                             __float_as_uint(bf.x), __float_as_uint(bf.y));
                    mma_tf32(d0, d1, d2, d3, a10, a11, a12, a13,
                             __float_as_uint(bf.z), __float_as_uint(bf.w));
                    d0 = fmaxf(d0, 0.0f); d1 = fmaxf(d1, 0.0f);
                    d2 = fmaxf(d2, 0.0f); d3 = fmaxf(d3, 0.0f);
                    acc[tsub] = fmaf(d0, m0.x, fmaf(d1, m0.y,
                                fmaf(d2, m1.x, fmaf(d3, m1.y, acc[tsub]))));
                }
            }
        }

        // Warp-reduce the 8 p-accumulators -> agg_sh[par][wq*8 + pi]
#pragma unroll
        for (int pi = 0; pi < 8; pi++) {
            float v = acc[pi];
#pragma unroll
            for (int o = 16; o; o >>= 1) v += __shfl_xor_sync(0xffffffffu, v, o);
            if (lane == 0) agg_sh[par * 32 + wq * 8 + pi] = v;
        }
        stream_bar(s);   // agg ready; E/mn free for next tile's staging
    }

    // ---- Drain: GRU for the last tile (warp 3) ----
    if (wq == 3 && ntt > 0) {
        const int tt = ntt - 1;
        const int ptile = gsid + tt * NSTREAMS_TOTAL;
        const int pb = ptile / Nc;
        const int pi = ptile - pb * Nc;
        const float* x1p  = x1_sh + tt * 32;
        const float* aggp = agg_sh + (tt & 1) * 32;
#pragma unroll
        for (int g3 = 0; g3 < 3; g3++) {
            const int gate = g3 * 32 + lane;
            float g = b_ih[gate];
#pragma unroll
            for (int d = 0; d < Dc; d++) g = fmaf(x1p[d], wihT[d * 96 + gate], g);
            gi_sh[gate] = g;
        }
        __syncwarp();
        {
            const float r = sigmoidf_(gi_sh[lane] + b_hh[lane]);
            const float z = sigmoidf_(gi_sh[32 + lane] + b_hh[32 + lane]);
            const float n = tanhf(gi_sh[64 + lane] + r * b_hh[64 + lane]);
            h1_sh[lane] = (1.0f - z) * n;
        }
        __syncwarp();
#pragma unroll
        for (int g3 = 0; g3 < 3; g3++) {
            const int gate = g3 * 32 + lane;
            float g  = b_ih[gate];
            float gh = b_hh[gate];
#pragma unroll
            for (int d = 0; d < Dc; d++) {
                g  = fmaf(aggp[d],  wihT[d * 96 + gate], g);
                gh = fmaf(h1_sh[d], whhT[d * 96 + gate], gh);
            }
            gi_sh[gate] = g;
            gh_sh[gate] = gh;
        }
        __syncwarp();
        {
            const float r = sigmoidf_(gi_sh[lane] + gh_sh[lane]);
            const float z = sigmoidf_(gi_sh[32 + lane] + gh_sh[32 + lane]);
            const float n = tanhf(gi_sh[64 + lane] + r * gh_sh[64 + lane]);
            out[((size_t)pb * Nc + pi) * Dc + lane] = (1.0f - z) * n + z * h1_sh[lane];
        }
    }
}

} // namespace

extern "C" void kernel_launch(void* const* d_in, const int* in_sizes, int n_in,
                              void* d_out, int out_size) {
    const float* nodes = (const float*)d_in[0];
    const float* edges = (const float*)d_in[1];
    const float* mask  = (const float*)d_in[2];
    const float* W_agg = (const float*)d_in[3];
    const float* b_agg = (const float*)d_in[4];
    const float* w_ih  = (const float*)d_in[5];
    const float* w_hh  = (const float*)d_in[6];
    const float* b_ih  = (const float*)d_in[7];
    const float* b_hh  = (const float*)d_in[8];
    float* out = (float*)d_out;

    cudaFuncSetAttribute(mp_layer_kernel,
                         cudaFuncAttributeMaxDynamicSharedMemorySize, SMEM_BYTES);
    mp_layer_kernel<<<GRID, THREADS, SMEM_BYTES>>>(nodes, edges, mask, W_agg, b_agg,
                                                   w_ih, w_hh, b_ih, b_hh, out);
}

// round 12
// speedup vs baseline: 4.6453x; 1.0485x over previous
#include <cuda_runtime.h>
#include <math.h>
#include <stdint.h>

__device__ int g_tile_counter;   // reset to 0 by kernel_launch each call

namespace {

constexpr int Bc = 32, Nc = 96, Dc = 32, Fc = 16;
constexpr int THREADS = 512;        // four independent 128-thread streams
constexpr int SWIDTH  = 128;
constexpr int NSTREAM = 4;
constexpr int GRID    = 152;        // persistent: 1 CTA per SM
constexpr int NTILES  = Bc * Nc;    // 3072
constexpr int NSTREAMS_TOTAL = GRID * NSTREAM;   // 608
constexpr int EPAD    = 20;

// Shared (read-only after init)
constexpr int OFF_WFRAG = 0;                 // float4[128 nt][32 lane] = 65536
constexpr int OFF_BIAS  = 65536;             // 1024 f = 4096
constexpr int OFF_WIH   = 69632;             // w_ih^T [32][96] = 12288
constexpr int OFF_WHH   = 81920;             // w_hh^T [32][96] = 12288
// Per-stream block
constexpr int OFF_S0  = 94208;
constexpr int SO_E    = 0;       // 96 x 20 u32 = 7680
constexpr int SO_MN   = 7680;    // 1536 float2 = 12288
constexpr int SO_ACT  = 19968;   // [2][96] int = 768   (parity double-buffer)
constexpr int SO_X1   = 20736;   // [2][32] f = 256
constexpr int SO_META = 20992;   // cnt[2], tile[2] = 16, pad 32
constexpr int SO_AGG  = 21024;   // [2][32] f = 256
constexpr int SO_GI   = 21280;   // 96 f
constexpr int SO_GH   = 21664;   // 96 f
constexpr int SO_H1   = 22048;   // 32 f
constexpr int S_BYTES = 22272;
constexpr int SMEM_BYTES = OFF_S0 + NSTREAM * S_BYTES;   // 183296

__device__ __forceinline__ float sigmoidf_(float x) { return 1.0f / (1.0f + expf(-x)); }

__device__ __forceinline__ uint32_t f2tf32(float x) {
    uint32_t r;
    asm("cvt.rna.tf32.f32 %0, %1;" : "=r"(r) : "f"(x));
    return r;
}

__device__ __forceinline__ void mma_tf32(float& d0, float& d1, float& d2, float& d3,
                                         uint32_t a0, uint32_t a1, uint32_t a2, uint32_t a3,
                                         uint32_t b0, uint32_t b1) {
    asm volatile(
        "mma.sync.aligned.m16n8k8.row.col.f32.tf32.tf32.f32 "
        "{%0,%1,%2,%3}, {%4,%5,%6,%7}, {%8,%9}, {%0,%1,%2,%3};"
        : "+f"(d0), "+f"(d1), "+f"(d2), "+f"(d3)
        : "r"(a0), "r"(a1), "r"(a2), "r"(a3), "r"(b0), "r"(b1));
}

// mn storage: (e,qp) -> float2 slot = ((qp>>2)*12 + (e>>3))*32 + (qp&3)*8 + (e&7)
__device__ __forceinline__ int mn_idx(int e, int qp) {
    return (((qp >> 2) * 12 + (e >> 3)) << 5) + ((qp & 3) << 3) + (e & 7);
}

__device__ __forceinline__ void stream_bar(int s) {
    asm volatile("bar.sync %0, %1;" :: "r"(s + 1), "r"(SWIDTH) : "memory");
}

// Warp-collective: compact active edges of tile t into slot p; stage x1.
__device__ __forceinline__ void compact_tile(int t, int p, int lane,
                                             const float* __restrict__ mask,
                                             const float* __restrict__ nodes,
                                             int* act_sh, int* cnt_sh, float* x1_sh) {
    const int b = t / Nc;
    const int i = t - b * Nc;
    const size_t mbase = (size_t)b * (Nc * Nc) + (size_t)i * Nc;
    int cnt = 0;
#pragma unroll
    for (int rr = 0; rr < Nc / 32; rr++) {
        const int j = rr * 32 + lane;
        const bool a = (mask[mbase + j] != 0.0f);
        const unsigned bal = __ballot_sync(0xffffffffu, a);
        if (a) act_sh[p * 96 + cnt + __popc(bal & ((1u << lane) - 1u))] = j;
        cnt += __popc(bal);
    }
    if (lane == 0) cnt_sh[p] = cnt;
    x1_sh[p * 32 + lane] = nodes[((size_t)b * Nc + i) * Dc + lane];
}

// Warp-collective GRU for one tile (warp 3 only).
__device__ __forceinline__ void gru_tile(int ptile, int lane,
                                         const float* x1p, const float* aggp,
                                         float* gi_sh, float* gh_sh, float* h1_sh,
                                         const float* wihT, const float* whhT,
                                         const float* __restrict__ b_ih,
                                         const float* __restrict__ b_hh,
                                         float* __restrict__ out) {
    const int pb = ptile / Nc;
    const int pi = ptile - pb * Nc;
#pragma unroll
    for (int g3 = 0; g3 < 3; g3++) {
        const int gate = g3 * 32 + lane;
        float g = b_ih[gate];
#pragma unroll
        for (int d = 0; d < Dc; d++) g = fmaf(x1p[d], wihT[d * 96 + gate], g);
        gi_sh[gate] = g;
    }
    __syncwarp();
    {
        const float r = sigmoidf_(gi_sh[lane] + b_hh[lane]);
        const float z = sigmoidf_(gi_sh[32 + lane] + b_hh[32 + lane]);
        const float n = tanhf(gi_sh[64 + lane] + r * b_hh[64 + lane]);
        h1_sh[lane] = (1.0f - z) * n;   // + z*h0, h0 = 0
    }
    __syncwarp();
#pragma unroll
    for (int g3 = 0; g3 < 3; g3++) {
        const int gate = g3 * 32 + lane;
        float g  = b_ih[gate];
        float gh = b_hh[gate];
#pragma unroll
        for (int d = 0; d < Dc; d++) {
            g  = fmaf(aggp[d],  wihT[d * 96 + gate], g);
            gh = fmaf(h1_sh[d], whhT[d * 96 + gate], gh);
        }
        gi_sh[gate] = g;
        gh_sh[gate] = gh;
    }
    __syncwarp();
    {
        const float r = sigmoidf_(gi_sh[lane] + gh_sh[lane]);
        const float z = sigmoidf_(gi_sh[32 + lane] + gh_sh[32 + lane]);
        const float n = tanhf(gi_sh[64 + lane] + r * gh_sh[64 + lane]);
        out[((size_t)pb * Nc + pi) * Dc + lane] = (1.0f - z) * n + z * h1_sh[lane];
    }
}

__global__ __launch_bounds__(THREADS, 1)
void mp_layer_kernel(const float* __restrict__ nodes,   // [B, N, D]
                     const float* __restrict__ edges,   // [B, N*N, F]
                     const float* __restrict__ mask,    // [B, N*N, 1] (0/1)
                     const float* __restrict__ W_agg,   // [F, D*D]
                     const float* __restrict__ b_agg,   // [D*D]
                     const float* __restrict__ w_ih,    // [3D, D]
                     const float* __restrict__ w_hh,    // [3D, D]
                     const float* __restrict__ b_ih,    // [3D]
                     const float* __restrict__ b_hh,    // [3D]
                     float* __restrict__ out)           // [B, N, D]
{
    extern __shared__ char smem[];
    float4* wfrag4  = reinterpret_cast<float4*>(smem + OFF_WFRAG);
    float*  bias_sh = reinterpret_cast<float*>(smem + OFF_BIAS);
    float*  wihT    = reinterpret_cast<float*>(smem + OFF_WIH);
    float*  whhT    = reinterpret_cast<float*>(smem + OFF_WHH);

    const int tid = threadIdx.x;

    // ---- One-time per CTA: W fragments (tf32, both k-steps packed), bias,
    //      transposed GRU weights ----
    for (int idx = tid; idx < 128 * 32; idx += THREADS) {
        const int l  = idx & 31;
        const int nt = idx >> 5;
        const int col = nt * 8 + (l >> 2);
        const int k   = l & 3;
        float4 v;
        v.x = __uint_as_float(f2tf32(W_agg[(k)      * 1024 + col]));
        v.y = __uint_as_float(f2tf32(W_agg[(k + 4)  * 1024 + col]));
        v.z = __uint_as_float(f2tf32(W_agg[(k + 8)  * 1024 + col]));
        v.w = __uint_as_float(f2tf32(W_agg[(k + 12) * 1024 + col]));
        wfrag4[idx] = v;
    }
    for (int c = tid; c < 1024; c += THREADS) bias_sh[c] = b_agg[c];
    for (int idx = tid; idx < 96 * 32; idx += THREADS) {
        const int g = idx >> 5;
        const int d = idx & 31;
        wihT[d * 96 + g] = w_ih[idx];
        whhT[d * 96 + g] = w_hh[idx];
    }
    __syncthreads();

    // ---- Stream-local views ----
    const int s    = tid >> 7;
    const int tids = tid & (SWIDTH - 1);
    const int lane = tid & 31;
    const int wq   = (tid >> 5) & 3;

    char* sbase = smem + OFF_S0 + s * S_BYTES;
    uint32_t* E_sh   = reinterpret_cast<uint32_t*>(sbase + SO_E);
    float2*   mnS    = reinterpret_cast<float2*>(sbase + SO_MN);
    int*      act_sh = reinterpret_cast<int*>(sbase + SO_ACT);
    float*    x1_sh  = reinterpret_cast<float*>(sbase + SO_X1);
    int*      cnt_sh = reinterpret_cast<int*>(sbase + SO_META);
    int*      tile_sh= reinterpret_cast<int*>(sbase + SO_META) + 2;
    float*    agg_sh = reinterpret_cast<float*>(sbase + SO_AGG);
    float*    gi_sh  = reinterpret_cast<float*>(sbase + SO_GI);
    float*    gh_sh  = reinterpret_cast<float*>(sbase + SO_GH);
    float*    h1_sh  = reinterpret_cast<float*>(sbase + SO_H1);

    const int gsid = blockIdx.x * NSTREAM + s;

    // ---- Prefetch: warp 3 compacts the stream's static first tile ----
    if (wq == 3) {
        if (lane == 0) tile_sh[0] = gsid;
        compact_tile(gsid, 0, lane, mask, nodes, act_sh, cnt_sh, x1_sh);
    }
    stream_bar(s);

    // Lane constants for the mainloop
    const int l4   = lane & 3;
    const int lr   = lane >> 2;
    const int mnlo = (l4 << 3) + (lr & 7);
    const int lrh  = lr >> 3;

    // ---- Dynamic pipelined tile loop ----
    int it = 0;
    while (true) {
        const int par = it & 1;
        const int cur = tile_sh[par];
        if (cur >= NTILES) break;                 // stream-uniform

        const int b = cur / Nc;
        const int i = cur - b * Nc;
        const size_t ebase = ((size_t)b * (Nc * Nc) + (size_t)i * Nc) * Fc;
        const size_t nbase = (size_t)b * (Nc * Dc);
        const int cnt    = cnt_sh[par];
        const int mtiles = (cnt + 15) >> 4;
        const int padcnt = mtiles << 4;

        if (wq < 3) {
            // Warps 0-2: stage E_act (tf32, float4-vectorized) and mn.
            const int* act = act_sh + par * 96;
            for (int idx = tids; idx < padcnt * 4; idx += 96) {
                const int a  = idx >> 2;
                const int f4 = (idx & 3) << 2;
                uint4 o = make_uint4(0u, 0u, 0u, 0u);
                if (a < cnt) {
                    const float4 v = *reinterpret_cast<const float4*>(
                        edges + ebase + (size_t)act[a] * Fc + f4);
                    o.x = f2tf32(v.x); o.y = f2tf32(v.y);
                    o.z = f2tf32(v.z); o.w = f2tf32(v.w);
                }
                *reinterpret_cast<uint4*>(E_sh + a * EPAD + f4) = o;
            }
            for (int idx = tids; idx < padcnt * 8; idx += 96) {
                const int a  = idx >> 3;
                const int q2 = (idx & 7) << 1;    // qp pair: q2, q2+1
                float4 v = make_float4(0.f, 0.f, 0.f, 0.f);
                if (a < cnt) {
                    v = *reinterpret_cast<const float4*>(
                        nodes + nbase + (size_t)act[a] * Dc + q2 * 2);
                }
                mnS[mn_idx(a, q2)]     = make_float2(v.x, v.y);
                mnS[mn_idx(a, q2 + 1)] = make_float2(v.z, v.w);
            }
        } else {
            // Warp 3: GRU(tile of previous iteration), then grab + compact next.
            if (it > 0) {
                const int pp = (it - 1) & 1;
                gru_tile(tile_sh[pp], lane, x1_sh + pp * 32, agg_sh + pp * 32,
                         gi_sh, gh_sh, h1_sh, wihT, whhT, b_ih, b_hh, out);
            }
            int nxt;
            if (lane == 0) nxt = NSTREAMS_TOTAL + atomicAdd(&g_tile_counter, 1);
            nxt = __shfl_sync(0xffffffffu, nxt, 0);
            const int np = (it + 1) & 1;
            if (lane == 0) tile_sh[np] = nxt;
            if (nxt < NTILES)
                compact_tile(nxt, np, lane, mask, nodes, act_sh, cnt_sh, x1_sh);
        }
        stream_bar(s);   // staging done, GRU done, next tile compacted

        // ---- MMA + fused epilogue (all 4 warps); pair-blocked m loop ----
        float acc[8] = {0.f, 0.f, 0.f, 0.f, 0.f, 0.f, 0.f, 0.f};

        int mt = 0;
        for (; mt + 2 <= mtiles; mt += 2) {
            const int r0 = mt * 16 + lr;
            const uint32_t* e0p = E_sh + r0 * EPAD;
            const uint32_t a00 = e0p[l4],            a01 = e0p[8*EPAD + l4];
            const uint32_t a02 = e0p[l4 + 4],        a03 = e0p[8*EPAD + l4 + 4];
            const uint32_t a10 = e0p[l4 + 8],        a11 = e0p[8*EPAD + l4 + 8];
            const uint32_t a12 = e0p[l4 + 12],       a13 = e0p[8*EPAD + l4 + 12];
            const uint32_t b00 = e0p[16*EPAD + l4],      b01 = e0p[24*EPAD + l4];
            const uint32_t b02 = e0p[16*EPAD + l4 + 4],  b03 = e0p[24*EPAD + l4 + 4];
            const uint32_t b10 = e0p[16*EPAD + l4 + 8],  b11 = e0p[24*EPAD + l4 + 8];
            const uint32_t b12 = e0p[16*EPAD + l4 + 12], b13 = e0p[24*EPAD + l4 + 12];
            const int blk0 = mt * 2 + lrh;

#pragma unroll
            for (int c = 0; c < 4; c++) {
                const float2* mp = mnS + ((c * 12 + blk0) << 5) + mnlo;
                const float2 m0 = mp[0];
                const float2 m1 = mp[32];
                const float2 m2 = mp[64];
                const float2 m3 = mp[96];
                const float4* wp = wfrag4 + (wq * 32 + c) * 32 + lane;
                const float2* bp = reinterpret_cast<const float2*>(
                    bias_sh + wq * 256 + c * 8 + l4 * 2);
#pragma unroll
                for (int tsub = 0; tsub < 8; tsub++) {
                    const float4 bf = *wp;  wp += 128;
                    const float2 bb = *bp;  bp += 16;
                    float d0 = bb.x, d1 = bb.y, d2 = bb.x, d3 = bb.y;
                    float f0 = bb.x, f1 = bb.y, f2 = bb.x, f3 = bb.y;
                    mma_tf32(d0, d1, d2, d3, a00, a01, a02, a03,
                             __float_as_uint(bf.x), __float_as_uint(bf.y));
                    mma_tf32(d0, d1, d2, d3, a10, a11, a12, a13,
                             __float_as_uint(bf.z), __float_as_uint(bf.w));
                    mma_tf32(f0, f1, f2, f3, b00, b01, b02, b03,
                             __float_as_uint(bf.x), __float_as_uint(bf.y));
                    mma_tf32(f0, f1, f2, f3, b10, b11, b12, b13,
                             __float_as_uint(bf.z), __float_as_uint(bf.w));
                    d0 = fmaxf(d0, 0.0f); d1 = fmaxf(d1, 0.0f);
                    d2 = fmaxf(d2, 0.0f); d3 = fmaxf(d3, 0.0f);
                    f0 = fmaxf(f0, 0.0f); f1 = fmaxf(f1, 0.0f);
                    f2 = fmaxf(f2, 0.0f); f3 = fmaxf(f3, 0.0f);
                    float v = fmaf(d0, m0.x, fmaf(d1, m0.y,
                              fmaf(d2, m1.x, fmaf(d3, m1.y, acc[tsub]))));
                    acc[tsub] = fmaf(f0, m2.x, fmaf(f1, m2.y,
                                fmaf(f2, m3.x, fmaf(f3, m3.y, v))));
                }
            }
        }
        if (mt < mtiles) {   // single-block tail (odd mtiles)
            const int r0 = mt * 16 + lr;
            const uint32_t* e0p = E_sh + r0 * EPAD;
            const uint32_t a00 = e0p[l4],      a01 = e0p[8*EPAD + l4];
            const uint32_t a02 = e0p[l4 + 4],  a03 = e0p[8*EPAD + l4 + 4];
            const uint32_t a10 = e0p[l4 + 8],  a11 = e0p[8*EPAD + l4 + 8];
            const uint32_t a12 = e0p[l4 + 12], a13 = e0p[8*EPAD + l4 + 12];
            const int blk0 = mt * 2 + lrh;
#pragma unroll
            for (int c = 0; c < 4; c++) {
                const float2* mp = mnS + ((c * 12 + blk0) << 5) + mnlo;
                const float2 m0 = mp[0];
                const float2 m1 = mp[32];
                const float4* wp = wfrag4 + (wq * 32 + c) * 32 + lane;
                const float2* bp = reinterpret_cast<const float2*>(
                    bias_sh + wq * 256 + c * 8 + l4 * 2);
#pragma unroll
                for (int tsub = 0; tsub < 8; tsub++) {
                    const float4 bf = *wp;  wp += 128;
                    const float2 bb = *bp;  bp += 16;
                    float d0 = bb.x, d1 = bb.y, d2 = bb.x, d3 = bb.y;
                    mma_tf32(d0, d1, d2, d3, a00, a01, a02, a03,
                             __float_as_uint(bf.x), __float_as_uint(bf.y));
                    mma_tf32(d0, d1, d2, d3, a10, a11, a12, a13,
                             __float_as_uint(bf.z), __float_as_uint(bf.w));
                    d0 = fmaxf(d0, 0.0f); d1 = fmaxf(d1, 0.0f);
                    d2 = fmaxf(d2, 0.0f); d3 = fmaxf(d3, 0.0f);
                    acc[tsub] = fmaf(d0, m0.x, fmaf(d1, m0.y,
                                fmaf(d2, m1.x, fmaf(d3, m1.y, acc[tsub]))));
                }
            }
        }

        // Warp-reduce the 8 p-accumulators -> agg_sh[par][wq*8 + pi]
#pragma unroll
        for (int pi = 0; pi < 8; pi++) {
            float v = acc[pi];
#pragma unroll
            for (int o = 16; o; o >>= 1) v += __shfl_xor_sync(0xffffffffu, v, o);
            if (lane == 0) agg_sh[par * 32 + wq * 8 + pi] = v;
        }
        stream_bar(s);   // agg ready; E/mn free; tile_sh[next] visible
        it++;
    }

    // ---- Drain: GRU for the last processed tile ----
    if (wq == 3 && it > 0) {
        const int pp = (it - 1) & 1;
        gru_tile(tile_sh[pp], lane, x1_sh + pp * 32, agg_sh + pp * 32,
                 gi_sh, gh_sh, h1_sh, wihT, whhT, b_ih, b_hh, out);
    }
}

} // namespace

extern "C" void kernel_launch(void* const* d_in, const int* in_sizes, int n_in,
                              void* d_out, int out_size) {
    const float* nodes = (const float*)d_in[0];
    const float* edges = (const float*)d_in[1];
    const float* mask  = (const float*)d_in[2];
    const float* W_agg = (const float*)d_in[3];
    const float* b_agg = (const float*)d_in[4];
    const float* w_ih  = (const float*)d_in[5];
    const float* w_hh  = (const float*)d_in[6];
    const float* b_ih  = (const float*)d_in[7];
    const float* b_hh  = (const float*)d_in[8];
    float* out = (float*)d_out;

    void* ctr = nullptr;
    cudaGetSymbolAddress(&ctr, g_tile_counter);
    cudaMemsetAsync(ctr, 0, sizeof(int));

    cudaFuncSetAttribute(mp_layer_kernel,
                         cudaFuncAttributeMaxDynamicSharedMemorySize, SMEM_BYTES);
    mp_layer_kernel<<<GRID, THREADS, SMEM_BYTES>>>(nodes, edges, mask, W_agg, b_agg,
                                                   w_ih, w_hh, b_ih, b_hh, out);
}